// round 12
// baseline (speedup 1.0000x reference)
#include <cuda_runtime.h>
#include <cstdint>

// ---------------- problem dims ----------------
#define B_    64
#define T_    100
#define INF_  700
#define RED_  256
#define WID_  4096
#define CLS_  20
#define ROWS_ (B_*T_)          // 6400
#define KC_   1280             // conv im2col K (256*5)
#define NELEM_ (ROWS_*WID_)    // 26214400
#define WCAP  (1u<<22)
#define MARGIN 2.5e-3f

#define N0_ (RED_*INF_)        // 179200
#define N1_ (WID_*RED_)        // 1048576
#define N2_ (CLS_*WID_)        // 81920
#define N3_ (RED_*KC_)         // 327680
#define NPREP_ (N0_+N1_+N2_+N3_)   // 1637376 = 6396*256

// ---------------- scratch (static device globals; no alloc allowed) ----------------
__device__ unsigned g_absmax[4];
__device__ unsigned g_count;
__device__ unsigned g_worklist[WCAP];
__device__ float  g_decay[T_];
__device__ float  g_qsp[RED_*INF_];
__device__ float  g_qfc1[WID_*RED_];      // exact scale*k (fixup)
__device__ float  g_qk[WID_*RED_];        // integer k as float (tf32-exact)
__device__ float  g_qfc2[CLS_*WID_];
__device__ float  g_convWt[RED_*KC_];
__device__ float  g_xp[ROWS_*RED_];
__device__ float  g_co[ROWS_*RED_];       // exact (fixup)
__device__ float  g_coh[ROWS_*RED_];      // tf32 hi of co
__device__ float  g_wsum[B_*WID_];

// ---------------- threefry2x32 (JAX-compatible, partitionable mode) ----------------
__host__ __device__ constexpr unsigned rotl32c(unsigned v, int s) {
    return (v << s) | (v >> (32 - s));
}
struct K2 { unsigned a, b; };
constexpr K2 tf_const(unsigned k0, unsigned k1, unsigned x0, unsigned x1) {
    unsigned ks2 = k0 ^ k1 ^ 0x1BD11BDAu;
    unsigned ks[3] = {k0, k1, ks2};
    x0 += k0; x1 += k1;
    const int R[20] = {13,15,26,6, 17,29,16,24, 13,15,26,6, 17,29,16,24, 13,15,26,6};
    for (int g = 0; g < 5; ++g) {
        for (int j = 0; j < 4; ++j) { x0 += x1; x1 = rotl32c(x1, R[g*4+j]); x1 ^= x0; }
        x0 += ks[(g+1)%3];
        x1 += ks[(g+2)%3] + (unsigned)(g+1);
    }
    return K2{x0, x1};
}
constexpr K2 SUBKEY = tf_const(0u, 42u, 0u, 1u);
constexpr unsigned SK0 = SUBKEY.a;
constexpr unsigned SK1 = SUBKEY.b;

__device__ __forceinline__ uint2 tf2x32(unsigned k0, unsigned k1, unsigned x0, unsigned x1) {
    unsigned ks2 = k0 ^ k1 ^ 0x1BD11BDAu;
    x0 += k0; x1 += k1;
#define TFR(r) { x0 += x1; x1 = __funnelshift_l(x1, x1, (r)); x1 ^= x0; }
    TFR(13) TFR(15) TFR(26) TFR(6)   x0 += k1;  x1 += ks2 + 1u;
    TFR(17) TFR(29) TFR(16) TFR(24)  x0 += ks2; x1 += k0  + 2u;
    TFR(13) TFR(15) TFR(26) TFR(6)   x0 += k0;  x1 += k1  + 3u;
    TFR(17) TFR(29) TFR(16) TFR(24)  x0 += k1;  x1 += ks2 + 4u;
    TFR(13) TFR(15) TFR(26) TFR(6)   x0 += ks2; x1 += k0  + 5u;
#undef TFR
    return make_uint2(x0, x1);
}
__device__ __forceinline__ unsigned rbits32(unsigned idx) {
    uint2 r = tf2x32(SK0, SK1, 0u, idx);
    return r.x ^ r.y;
}

// ---------------- packed f32x2 helpers ----------------
__device__ __forceinline__ void ffma2(unsigned long long& acc,
                                      unsigned long long a,
                                      unsigned long long b) {
    asm("fma.rn.f32x2 %0, %1, %2, %0;" : "+l"(acc) : "l"(a), "l"(b));
}
__device__ __forceinline__ unsigned long long dup_f32x2(float x) {
    unsigned long long d;
    asm("mov.b64 %0, {%1, %1};" : "=l"(d) : "f"(x));
    return d;
}
__device__ __forceinline__ float2 unpack_f32x2(unsigned long long v) {
    float lo, hi;
    asm("mov.b64 {%0, %1}, %2;" : "=f"(lo), "=f"(hi) : "l"(v));
    return make_float2(lo, hi);
}

// ---------------- tf32 helpers ----------------
__device__ __forceinline__ float tf32_hi(float x) {
    uint32_t u; asm("cvt.rna.tf32.f32 %0, %1;" : "=r"(u) : "f"(x));
    return __uint_as_float(u);
}
#define MMA_TF32(c, a, b) \
    asm volatile("mma.sync.aligned.m16n8k8.row.col.f32.tf32.tf32.f32 " \
        "{%0,%1,%2,%3}, {%4,%5,%6,%7}, {%8,%9}, {%0,%1,%2,%3};" \
        : "+f"((c)[0]), "+f"((c)[1]), "+f"((c)[2]), "+f"((c)[3]) \
        : "r"(__float_as_uint((a)[0])), "r"(__float_as_uint((a)[1])), \
          "r"(__float_as_uint((a)[2])), "r"(__float_as_uint((a)[3])), \
          "r"(__float_as_uint((b)[0])), "r"(__float_as_uint((b)[1])))

__device__ __forceinline__ uint32_t smem_u32(const void* p) {
    uint32_t a;
    asm("{ .reg .u64 t; cvta.to.shared.u64 t, %1; cvt.u32.u64 %0, t; }" : "=r"(a) : "l"(p));
    return a;
}
#define CP_ASYNC16(s, g) \
    asm volatile("cp.async.cg.shared.global [%0], [%1], 16;" :: "r"(s), "l"(g))
#define CP_COMMIT()  asm volatile("cp.async.commit_group;")
#define CP_WAIT0()   asm volatile("cp.async.wait_group 0;")

// ---------------- prep kernels ----------------
__global__ void init_k() {
    if (threadIdx.x < 4) g_absmax[threadIdx.x] = 0u;
    if (threadIdx.x == 0) g_count = 0u;
    if (threadIdx.x < T_)
        g_decay[threadIdx.x] = expf(-2.0f + (float)threadIdx.x * (2.0f/99.0f));
}
// merged absmax over 3 tensors
__global__ void absmax3_k(const float* __restrict__ W0, const float* __restrict__ W1,
                          const float* __restrict__ W2) {
    const float* W; int n, which, b0, nb;
    if (blockIdx.x < 64)        { W = W0; n = N0_; which = 0; b0 = 0;   nb = 64;  }
    else if (blockIdx.x < 320)  { W = W1; n = N1_; which = 1; b0 = 64;  nb = 256; }
    else                        { W = W2; n = N2_; which = 2; b0 = 320; nb = 64;  }
    float m = 0.0f;
    for (int i = (int)(blockIdx.x - b0)*blockDim.x + threadIdx.x; i < n; i += nb*blockDim.x)
        m = fmaxf(m, fabsf(W[i]));
    #pragma unroll
    for (int o = 16; o; o >>= 1) m = fmaxf(m, __shfl_xor_sync(0xffffffffu, m, o));
    if ((threadIdx.x & 31) == 0) atomicMax(&g_absmax[which], __float_as_uint(m));
}
// merged quantization + conv transpose
__global__ void prep_k(const float* __restrict__ spW, const float* __restrict__ fc1W,
                       const float* __restrict__ fc2W, const float* __restrict__ convW) {
    int i = blockIdx.x*blockDim.x + threadIdx.x;
    if (i < N0_) {
        float scale = fmaxf(__fdiv_rn(__uint_as_float(g_absmax[0]), 7.0f), 1e-8f);
        g_qsp[i] = __fmul_rn(rintf(__fdiv_rn(spW[i], scale)), scale);
    } else if (i < N0_ + N1_) {
        int j = i - N0_;
        float scale = fmaxf(__fdiv_rn(__uint_as_float(g_absmax[1]), 7.0f), 1e-8f);
        float k = rintf(__fdiv_rn(fc1W[j], scale));
        g_qfc1[j] = __fmul_rn(k, scale);
        g_qk[j]   = k;
    } else if (i < N0_ + N1_ + N2_) {
        int j = i - N0_ - N1_;
        float scale = fmaxf(__fdiv_rn(__uint_as_float(g_absmax[2]), 7.0f), 1e-8f);
        g_qfc2[j] = __fmul_rn(rintf(__fdiv_rn(fc2W[j], scale)), scale);
    } else {
        int j = i - N0_ - N1_ - N2_;
        int o = j / KC_, rem = j % KC_;
        int k = rem >> 8, c = rem & 255;
        g_convWt[j] = convW[o*KC_ + c*5 + k];
    }
}

// ---------------- FFMA2 double-buffered SGEMM 128x32x16 (exact fp32) -----------------
// 128 threads = 4 warps (32x32 each, stacked along M), per-thread 8x8, occ 4.
template<int CONV>
__device__ __forceinline__ float4 ldA(const float* __restrict__ A, int K, int row, int c) {
    if (CONV) {
        int tap = c >> 8, chn = c & 255;
        int b = row / T_, t = row - b*T_;
        int ts = t + tap - 2;
        if (ts < 0 || ts >= T_) return make_float4(0,0,0,0);
        return *reinterpret_cast<const float4*>(A + (size_t)(b*T_ + ts)*RED_ + chn);
    } else {
        if (c >= K) return make_float4(0,0,0,0);
        return *reinterpret_cast<const float4*>(A + (size_t)row*K + c);
    }
}

template<int CONV, int SPLIT>
__global__ __launch_bounds__(128, 4)
void sgemm_k(const float* __restrict__ A, const float* __restrict__ B,
             const float* __restrict__ bias, float* __restrict__ C,
             float* __restrict__ Ch, int K, int N)
{
    __shared__ float sA[2][16][128];
    __shared__ float sB[2][16][36];   // stride 36 floats: 144B rows keep 16B alignment

    const int tid  = threadIdx.x;
    const int lane = tid & 31;
    const int wid  = tid >> 5;        // 0..3
    const int lr   = lane >> 2;
    const int lc   = lane & 3;
    const int wm   = wid * 32;
    const int bm0  = blockIdx.y * 128, bn0 = blockIdx.x * 32;

    unsigned long long acc2[2][2][4][2];
    #pragma unroll
    for (int im = 0; im < 2; ++im)
        #pragma unroll
        for (int in = 0; in < 2; ++in)
            #pragma unroll
            for (int i = 0; i < 4; ++i) {
                acc2[im][in][i][0] = 0ull;
                acc2[im][in][i][1] = 0ull;
            }

    const int nch = (K + 15) >> 4;
    float4 va[4], vb;

    {   // prologue chunk 0
        #pragma unroll
        for (int i = 0; i < 4; ++i) {
            int q = tid + 128*i;
            int row = q >> 2, c = (q & 3) * 4;
            va[i] = ldA<CONV>(A, K, bm0 + row, c);
        }
        {
            int row = tid >> 2, c = (tid & 3) * 4;
            vb = (c < K) ? *reinterpret_cast<const float4*>(B + (size_t)(bn0+row)*K + c)
                         : make_float4(0,0,0,0);
        }
        #pragma unroll
        for (int i = 0; i < 4; ++i) {
            int q = tid + 128*i;
            int row = q >> 2, c4 = (q & 3) * 4;
            sA[0][c4+0][row] = va[i].x; sA[0][c4+1][row] = va[i].y;
            sA[0][c4+2][row] = va[i].z; sA[0][c4+3][row] = va[i].w;
        }
        {
            int row = tid >> 2, c4 = (tid & 3) * 4;
            sB[0][c4+0][row] = vb.x; sB[0][c4+1][row] = vb.y;
            sB[0][c4+2][row] = vb.z; sB[0][c4+3][row] = vb.w;
        }
        __syncthreads();
    }

    int p = 0;
    for (int ch = 0; ch < nch; ++ch) {
        const bool more = (ch + 1 < nch);
        if (more) {
            int k0 = (ch + 1) * 16;
            #pragma unroll
            for (int i = 0; i < 4; ++i) {
                int q = tid + 128*i;
                int row = q >> 2, c = k0 + (q & 3) * 4;
                va[i] = ldA<CONV>(A, K, bm0 + row, c);
            }
            {
                int row = tid >> 2, c = k0 + (tid & 3) * 4;
                vb = (c < K) ? *reinterpret_cast<const float4*>(B + (size_t)(bn0+row)*K + c)
                             : make_float4(0,0,0,0);
            }
        }
        #pragma unroll
        for (int kk = 0; kk < 16; ++kk) {
            float4 a0 = *reinterpret_cast<const float4*>(&sA[p][kk][wm + lr*4]);
            float4 a1 = *reinterpret_cast<const float4*>(&sA[p][kk][((wm + 32) & 127) + lr*4]);
            ulonglong2 b0 = *reinterpret_cast<const ulonglong2*>(&sB[p][kk][lc*4]);
            ulonglong2 b1 = *reinterpret_cast<const ulonglong2*>(&sB[p][kk][16 + lc*4]);
            unsigned long long bp[2][2] = { { b0.x, b0.y }, { b1.x, b1.y } };
            const float av[2][4] = { { a0.x, a0.y, a0.z, a0.w },
                                     { a1.x, a1.y, a1.z, a1.w } };
            #pragma unroll
            for (int im = 0; im < 2; ++im)
                #pragma unroll
                for (int i = 0; i < 4; ++i) {
                    unsigned long long ad = dup_f32x2(av[im][i]);
                    #pragma unroll
                    for (int in = 0; in < 2; ++in) {
                        ffma2(acc2[im][in][i][0], ad, bp[in][0]);
                        ffma2(acc2[im][in][i][1], ad, bp[in][1]);
                    }
                }
        }
        if (more) {
            int q2 = p ^ 1;
            #pragma unroll
            for (int i = 0; i < 4; ++i) {
                int q = tid + 128*i;
                int row = q >> 2, c4 = (q & 3) * 4;
                sA[q2][c4+0][row] = va[i].x; sA[q2][c4+1][row] = va[i].y;
                sA[q2][c4+2][row] = va[i].z; sA[q2][c4+3][row] = va[i].w;
            }
            {
                int row = tid >> 2, c4 = (tid & 3) * 4;
                sB[q2][c4+0][row] = vb.x; sB[q2][c4+1][row] = vb.y;
                sB[q2][c4+2][row] = vb.z; sB[q2][c4+3][row] = vb.w;
            }
            __syncthreads();
            p = q2;
        }
    }

    // epilogue: rows wm + im*32... NOTE im indexes (wm, wm+32)&127: im=0 -> wm, im=1 -> (wm+32)&127
    #pragma unroll
    for (int im = 0; im < 2; ++im)
        #pragma unroll
        for (int i = 0; i < 4; ++i) {
            int rloc = ((wm + im*32) & 127) + lr*4 + i;
            int row = bm0 + rloc;
            #pragma unroll
            for (int in = 0; in < 2; ++in) {
                int col = bn0 + in*16 + lc*4;
                float2 p01 = unpack_f32x2(acc2[im][in][i][0]);
                float2 p23 = unpack_f32x2(acc2[im][in][i][1]);
                float4 v;
                v.x = fmaxf(p01.x + __ldg(bias + col + 0), 0.0f);
                v.y = fmaxf(p01.y + __ldg(bias + col + 1), 0.0f);
                v.z = fmaxf(p23.x + __ldg(bias + col + 2), 0.0f);
                v.w = fmaxf(p23.y + __ldg(bias + col + 3), 0.0f);
                *reinterpret_cast<float4*>(C + (size_t)row*N + col) = v;
                if (SPLIT) {
                    float4 hv;
                    hv.x = tf32_hi(v.x); hv.y = tf32_hi(v.y);
                    hv.z = tf32_hi(v.z); hv.w = tf32_hi(v.w);
                    *reinterpret_cast<float4*>(Ch + (size_t)row*N + col) = hv;
                }
            }
        }
}

// ---------------- GEMM2: 1-pass tf32 (A = tf32(co), B = int4 levels) ------------------
#define AST 20
#define ASZ (128*AST)
#define BSZ (64*AST)
#define G2_SMEM ((2*ASZ + 2*BSZ)*4)     // 30720 B

__device__ __forceinline__ void g2_issue(const float* __restrict__ coh,
                                         const float* __restrict__ qk,
                                         uint32_t sAa, uint32_t sBa,
                                         int bm0, int bn0, int k0, int tid) {
    #pragma unroll
    for (int i = 0; i < 2; ++i) {
        int cid = tid + 256*i;
        int row = cid >> 2, kq = (cid & 3) * 4;
        const float* g = coh + (size_t)(bm0+row)*RED_ + k0 + kq;
        CP_ASYNC16(sAa + (uint32_t)((row*AST + kq) * 4), g);
    }
    {
        int row = tid >> 2, kq = (tid & 3) * 4;
        const float* g = qk + (size_t)(bn0+row)*RED_ + k0 + kq;
        CP_ASYNC16(sBa + (uint32_t)((row*AST + kq) * 4), g);
    }
    CP_COMMIT();
}

__global__ __launch_bounds__(256, 3)
void g2tf_k(const float* __restrict__ coh, const float* __restrict__ qk,
            const float* __restrict__ bias,
            const float* __restrict__ latent, const float* __restrict__ gainp,
            float* __restrict__ drv, float* __restrict__ spk)
{
    extern __shared__ float smf[];
    const uint32_t smem_base = smem_u32(smf);
    float* smB = smf + 2*ASZ;

    const int tid  = threadIdx.x;
    const int lane = tid & 31;
    const int wid  = tid >> 5;
    const int wm   = (wid & 3) * 32;
    const int wn   = (wid >> 2) * 32;
    const int bm0  = blockIdx.y * 128, bn0 = blockIdx.x * 64;

    float acc[2][4][4];
    #pragma unroll
    for (int mi = 0; mi < 2; ++mi)
        #pragma unroll
        for (int ni = 0; ni < 4; ++ni)
            #pragma unroll
            for (int q = 0; q < 4; ++q) acc[mi][ni][q] = 0.0f;

    g2_issue(coh, qk, smem_base, smem_base + 2*ASZ*4, bm0, bn0, 0, tid);

    #pragma unroll 1
    for (int ch = 0; ch < 16; ++ch) {
        CP_WAIT0();
        __syncthreads();
        const int p = ch & 1;
        if (ch + 1 < 16) {
            const int q2 = p ^ 1;
            g2_issue(coh, qk, smem_base + q2*ASZ*4,
                     smem_base + (2*ASZ + q2*BSZ)*4, bm0, bn0, (ch+1)*16, tid);
        }
        const float* A2 = smf + p*ASZ;
        const float* B2 = smB + p*BSZ;
        #pragma unroll
        for (int ksl = 0; ksl < 2; ++ksl) {
            const int bc = ksl*8 + (lane & 3);
            float afr[2][4];
            #pragma unroll
            for (int mi = 0; mi < 2; ++mi) {
                int r = wm + (lane >> 2) + mi*16;
                afr[mi][0] = A2[r*AST + bc];
                afr[mi][1] = A2[(r+8)*AST + bc];
                afr[mi][2] = A2[r*AST + bc + 4];
                afr[mi][3] = A2[(r+8)*AST + bc + 4];
            }
            float bfr[4][2];
            #pragma unroll
            for (int ni = 0; ni < 4; ++ni) {
                int n = wn + ni*8 + (lane >> 2);
                bfr[ni][0] = B2[n*AST + bc];
                bfr[ni][1] = B2[n*AST + bc + 4];
            }
            #pragma unroll
            for (int mi = 0; mi < 2; ++mi)
                #pragma unroll
                for (int ni = 0; ni < 4; ++ni)
                    MMA_TF32(acc[mi][ni], afr[mi], bfr[ni]);
        }
    }

    const int r0 = bm0 + wm + (lane >> 2);
    const int c0 = bn0 + wn + (lane & 3)*2;
    const float gabs = fabsf(gainp[0]);
    const float scaleB = fmaxf(__fdiv_rn(__uint_as_float(g_absmax[1]), 7.0f), 1e-8f);

    #pragma unroll
    for (int mi = 0; mi < 2; ++mi)
        #pragma unroll
        for (int ni = 0; ni < 4; ++ni) {
            int col = c0 + ni*8;
            float b0 = __ldg(bias + col), b1 = __ldg(bias + col + 1);
            #pragma unroll
            for (int h = 0; h < 2; ++h) {
                int row = r0 + mi*16 + h*8;
                float lat = __ldg(latent + (row % T_));
                float2 dv, sv;
                #pragma unroll
                for (int q = 0; q < 2; ++q) {
                    float pre = fmaf(acc[mi][ni][h*2+q], scaleB, q ? b1 : b0);
                    float e   = __expf(-fabsf(pre));
                    float sp  = fmaxf(pre, 0.0f) + __logf(1.0f + e);
                    float d   = (sp * lat) * gabs;
                    unsigned idx = (unsigned)row * (unsigned)WID_ + (unsigned)(col + q);
                    unsigned bits = rbits32(idx);
                    float u = __uint_as_float((bits >> 9) | 0x3f800000u) - 1.0f;
                    float spike;
                    if (d >= 10.0f) spike = 1.0f;
                    else {
                        float t = __expf(-d);
                        spike = (u > t) ? 1.0f : 0.0f;
                        if (fabsf(u - t) < MARGIN * t) {
                            unsigned w = atomicAdd(&g_count, 1u);
                            if (w < WCAP) g_worklist[w] = idx;
                        }
                    }
                    if (q) { dv.y = d; sv.y = spike; } else { dv.x = d; sv.x = spike; }
                }
                size_t ob = (size_t)row * WID_ + col;
                *reinterpret_cast<float2*>(drv + ob) = dv;
                *reinterpret_cast<float2*>(spk + ob) = sv;
            }
        }
}

// ---------------- exact fp32 fixup for borderline spikes (reference semantics) --------
__global__ void fixup_k(const float* __restrict__ co, const float* __restrict__ qfc1,
                        const float* __restrict__ bias, const float* __restrict__ latent,
                        const float* __restrict__ gainp, float* __restrict__ spk)
{
    __shared__ float red[4];
    const unsigned n = (g_count < WCAP) ? g_count : WCAP;
    const float gabs = fabsf(gainp[0]);
    const int tid = threadIdx.x;   // 128
    for (unsigned i = blockIdx.x; i < n; i += gridDim.x) {
        unsigned idx = g_worklist[i];
        int row = idx >> 12, col = idx & (WID_-1);
        const float* cr = co + (size_t)row * RED_;
        const float* wr = qfc1 + (size_t)col * RED_;
        float s = cr[tid]*wr[tid] + cr[tid+128]*wr[tid+128];
        #pragma unroll
        for (int o = 16; o; o >>= 1) s += __shfl_xor_sync(0xffffffffu, s, o);
        if ((tid & 31) == 0) red[tid >> 5] = s;
        __syncthreads();
        if (tid == 0) {
            float pre = (red[0]+red[1]) + (red[2]+red[3]) + bias[col];
            float spl = fmaxf(pre, 0.0f) + log1pf(expf(-fabsf(pre)));
            float d   = (spl * latent[row % T_]) * gabs;
            unsigned bits = rbits32(idx);
            float u = __uint_as_float((bits >> 9) | 0x3f800000u) - 1.0f;
            spk[idx] = (d >= 10.0f) ? 1.0f : ((logf(u) > -d) ? 1.0f : 0.0f);
        }
        __syncthreads();
    }
}

// ---------------- decay-weighted temporal reduction (latency-optimized) ---------------
__global__ void weighted_k(const float* __restrict__ spikes) {
    int idx = blockIdx.x * blockDim.x + threadIdx.x;
    if (idx >= B_*WID_) return;
    int b = idx >> 12, w = idx & (WID_-1);
    const float* sp = spikes + (size_t)b*T_*WID_ + w;
    float s0 = 0.0f, s1 = 0.0f, s2 = 0.0f, s3 = 0.0f;
    #pragma unroll
    for (int t = 0; t < T_; t += 4) {
        s0 = fmaf(__ldg(sp + (size_t)(t+0)*WID_), g_decay[t+0], s0);
        s1 = fmaf(__ldg(sp + (size_t)(t+1)*WID_), g_decay[t+1], s1);
        s2 = fmaf(__ldg(sp + (size_t)(t+2)*WID_), g_decay[t+2], s2);
        s3 = fmaf(__ldg(sp + (size_t)(t+3)*WID_), g_decay[t+3], s3);
    }
    g_wsum[idx] = (s0 + s1) + (s2 + s3);
}

// ---------------- logits ----------------
__global__ void logits_k(const float* __restrict__ bias, float* __restrict__ out) {
    int bc = blockIdx.x;
    int b = bc / CLS_, c = bc % CLS_;
    const float* wr = g_wsum + (size_t)b*WID_;
    const float* fr = g_qfc2 + (size_t)c*WID_;
    float s = 0.0f;
    for (int i = threadIdx.x; i < WID_; i += 128) s += wr[i]*fr[i];
    #pragma unroll
    for (int o = 16; o; o >>= 1) s += __shfl_xor_sync(0xffffffffu, s, o);
    __shared__ float red[4];
    if ((threadIdx.x & 31) == 0) red[threadIdx.x >> 5] = s;
    __syncthreads();
    if (threadIdx.x == 0) out[bc] = (red[0]+red[1]+red[2]+red[3]) + bias[c];
}

// ---------------- launcher ----------------
extern "C" void kernel_launch(void* const* d_in, const int* in_sizes, int n_in,
                              void* d_out, int out_size) {
    (void)in_sizes; (void)n_in; (void)out_size;
    const float* x        = (const float*)d_in[0];
    const float* latent   = (const float*)d_in[1];
    const float* spatialW = (const float*)d_in[2];
    const float* spatialB = (const float*)d_in[3];
    const float* convW    = (const float*)d_in[4];
    const float* convB    = (const float*)d_in[5];
    const float* fc1W     = (const float*)d_in[6];
    const float* fc1B     = (const float*)d_in[7];
    const float* fc2W     = (const float*)d_in[8];
    const float* fc2B     = (const float*)d_in[9];
    const float* gain     = (const float*)d_in[10];

    float* out        = (float*)d_out;
    float* out_logits = out;
    float* out_spk    = out + (CLS_*B_);
    float* out_drv    = out + (CLS_*B_) + (size_t)NELEM_;

    float *qsp, *qfc1, *qk, *qfc2, *cwt, *xp, *co, *coh;
    cudaGetSymbolAddress((void**)&qsp,  g_qsp);
    cudaGetSymbolAddress((void**)&qfc1, g_qfc1);
    cudaGetSymbolAddress((void**)&qk,   g_qk);
    cudaGetSymbolAddress((void**)&qfc2, g_qfc2);
    cudaGetSymbolAddress((void**)&cwt,  g_convWt);
    cudaGetSymbolAddress((void**)&xp,   g_xp);
    cudaGetSymbolAddress((void**)&co,   g_co);
    cudaGetSymbolAddress((void**)&coh,  g_coh);

    static bool attr_set = false;
    if (!attr_set) {
        cudaFuncSetAttribute(g2tf_k, cudaFuncAttributeMaxDynamicSharedMemorySize, G2_SMEM);
        attr_set = true;
    }

    init_k<<<1, 128>>>();
    absmax3_k<<<384, 256>>>(spatialW, fc1W, fc2W);
    prep_k<<<NPREP_/256, 256>>>(spatialW, fc1W, fc2W, convW);

    // GEMM1: xp = relu(x @ qsp^T + b)   (exact fp32 FFMA2, grid 8x50 = 400 CTAs)
    sgemm_k<0,0><<<dim3(RED_/32, ROWS_/128), 128>>>(x, qsp, spatialB, xp, nullptr, INF_, RED_);
    // conv (fused im2col): co = relu(im2col(xp) @ cwt^T + cb), also emits coh = tf32(co)
    sgemm_k<1,1><<<dim3(RED_/32, ROWS_/128), 128>>>(xp, cwt, convB, co, coh, KC_, RED_);
    // GEMM2 (tf32 1-pass, int4-level B, scale factored) + drive/spike + flags
    g2tf_k<<<dim3(WID_/64, ROWS_/128), 256, G2_SMEM>>>(coh, qk, fc1B,
                                                       latent, gain, out_drv, out_spk);
    // exact recompute of borderline spikes
    fixup_k<<<2048, 128>>>(co, qfc1, fc1B, latent, gain, out_spk);
    weighted_k<<<(B_*WID_ + 255)/256, 256>>>(out_spk);
    logits_k<<<B_*CLS_, 128>>>(fc2B, out_logits);
}

// round 14
// speedup vs baseline: 1.1458x; 1.1458x over previous
#include <cuda_runtime.h>
#include <cstdint>

// ---------------- problem dims ----------------
#define B_    64
#define T_    100
#define INF_  700
#define RED_  256
#define WID_  4096
#define CLS_  20
#define ROWS_ (B_*T_)          // 6400
#define KC_   1280             // conv im2col K (256*5)
#define NELEM_ (ROWS_*WID_)    // 26214400
#define WCAP  (1u<<22)
#define MARGIN 2.5e-3f

#define N0_ (RED_*INF_)        // 179200
#define N1_ (WID_*RED_)        // 1048576
#define N2_ (CLS_*WID_)        // 81920
#define N3_ (RED_*KC_)         // 327680
#define NPREP_ (N0_+N1_+N2_+N3_)   // 1637376 = 6396*256

// ---------------- scratch (static device globals; no alloc allowed) ----------------
__device__ unsigned g_absmax[4];
__device__ unsigned g_count;
__device__ unsigned g_worklist[WCAP];
__device__ float  g_decay[T_];
__device__ float  g_qsp[RED_*INF_];
__device__ float  g_qfc1[WID_*RED_];      // exact scale*k (fixup)
__device__ float  g_qk[WID_*RED_];        // integer k as float (tf32-exact)
__device__ float  g_qfc2[CLS_*WID_];
__device__ float  g_convWt[RED_*KC_];
__device__ float  g_xp[ROWS_*RED_];
__device__ float  g_co[ROWS_*RED_];       // exact (fixup)
__device__ float  g_coh[ROWS_*RED_];      // tf32 hi of co
__device__ float  g_wsum[B_*WID_];

// ---------------- threefry2x32 (JAX-compatible, partitionable mode) ----------------
__host__ __device__ constexpr unsigned rotl32c(unsigned v, int s) {
    return (v << s) | (v >> (32 - s));
}
struct K2 { unsigned a, b; };
constexpr K2 tf_const(unsigned k0, unsigned k1, unsigned x0, unsigned x1) {
    unsigned ks2 = k0 ^ k1 ^ 0x1BD11BDAu;
    unsigned ks[3] = {k0, k1, ks2};
    x0 += k0; x1 += k1;
    const int R[20] = {13,15,26,6, 17,29,16,24, 13,15,26,6, 17,29,16,24, 13,15,26,6};
    for (int g = 0; g < 5; ++g) {
        for (int j = 0; j < 4; ++j) { x0 += x1; x1 = rotl32c(x1, R[g*4+j]); x1 ^= x0; }
        x0 += ks[(g+1)%3];
        x1 += ks[(g+2)%3] + (unsigned)(g+1);
    }
    return K2{x0, x1};
}
constexpr K2 SUBKEY = tf_const(0u, 42u, 0u, 1u);
constexpr unsigned SK0 = SUBKEY.a;
constexpr unsigned SK1 = SUBKEY.b;

__device__ __forceinline__ uint2 tf2x32(unsigned k0, unsigned k1, unsigned x0, unsigned x1) {
    unsigned ks2 = k0 ^ k1 ^ 0x1BD11BDAu;
    x0 += k0; x1 += k1;
#define TFR(r) { x0 += x1; x1 = __funnelshift_l(x1, x1, (r)); x1 ^= x0; }
    TFR(13) TFR(15) TFR(26) TFR(6)   x0 += k1;  x1 += ks2 + 1u;
    TFR(17) TFR(29) TFR(16) TFR(24)  x0 += ks2; x1 += k0  + 2u;
    TFR(13) TFR(15) TFR(26) TFR(6)   x0 += k0;  x1 += k1  + 3u;
    TFR(17) TFR(29) TFR(16) TFR(24)  x0 += k1;  x1 += ks2 + 4u;
    TFR(13) TFR(15) TFR(26) TFR(6)   x0 += ks2; x1 += k0  + 5u;
#undef TFR
    return make_uint2(x0, x1);
}
__device__ __forceinline__ unsigned rbits32(unsigned idx) {
    uint2 r = tf2x32(SK0, SK1, 0u, idx);
    return r.x ^ r.y;
}

// ---------------- packed f32x2 helpers ----------------
__device__ __forceinline__ void ffma2(unsigned long long& acc,
                                      unsigned long long a,
                                      unsigned long long b) {
    asm("fma.rn.f32x2 %0, %1, %2, %0;" : "+l"(acc) : "l"(a), "l"(b));
}
__device__ __forceinline__ unsigned long long dup_f32x2(float x) {
    unsigned long long d;
    asm("mov.b64 %0, {%1, %1};" : "=l"(d) : "f"(x));
    return d;
}
__device__ __forceinline__ float2 unpack_f32x2(unsigned long long v) {
    float lo, hi;
    asm("mov.b64 {%0, %1}, %2;" : "=f"(lo), "=f"(hi) : "l"(v));
    return make_float2(lo, hi);
}

// ---------------- tf32 helpers ----------------
__device__ __forceinline__ float tf32_hi(float x) {
    uint32_t u; asm("cvt.rna.tf32.f32 %0, %1;" : "=r"(u) : "f"(x));
    return __uint_as_float(u);
}
#define MMA_TF32(c, a, b) \
    asm volatile("mma.sync.aligned.m16n8k8.row.col.f32.tf32.tf32.f32 " \
        "{%0,%1,%2,%3}, {%4,%5,%6,%7}, {%8,%9}, {%0,%1,%2,%3};" \
        : "+f"((c)[0]), "+f"((c)[1]), "+f"((c)[2]), "+f"((c)[3]) \
        : "r"(__float_as_uint((a)[0])), "r"(__float_as_uint((a)[1])), \
          "r"(__float_as_uint((a)[2])), "r"(__float_as_uint((a)[3])), \
          "r"(__float_as_uint((b)[0])), "r"(__float_as_uint((b)[1])))

__device__ __forceinline__ uint32_t smem_u32(const void* p) {
    uint32_t a;
    asm("{ .reg .u64 t; cvta.to.shared.u64 t, %1; cvt.u32.u64 %0, t; }" : "=r"(a) : "l"(p));
    return a;
}
#define CP_ASYNC16(s, g) \
    asm volatile("cp.async.cg.shared.global [%0], [%1], 16;" :: "r"(s), "l"(g))
#define CP_COMMIT()  asm volatile("cp.async.commit_group;")
#define CP_WAIT0()   asm volatile("cp.async.wait_group 0;")

// ---------------- prep kernels ----------------
__global__ void init_k() {
    if (threadIdx.x < 4) g_absmax[threadIdx.x] = 0u;
    if (threadIdx.x == 0) g_count = 0u;
    if (threadIdx.x < T_)
        g_decay[threadIdx.x] = expf(-2.0f + (float)threadIdx.x * (2.0f/99.0f));
}
// merged absmax over 3 tensors
__global__ void absmax3_k(const float* __restrict__ W0, const float* __restrict__ W1,
                          const float* __restrict__ W2) {
    const float* W; int n, which, b0, nb;
    if (blockIdx.x < 64)        { W = W0; n = N0_; which = 0; b0 = 0;   nb = 64;  }
    else if (blockIdx.x < 320)  { W = W1; n = N1_; which = 1; b0 = 64;  nb = 256; }
    else                        { W = W2; n = N2_; which = 2; b0 = 320; nb = 64;  }
    float m = 0.0f;
    for (int i = (int)(blockIdx.x - b0)*blockDim.x + threadIdx.x; i < n; i += nb*blockDim.x)
        m = fmaxf(m, fabsf(W[i]));
    #pragma unroll
    for (int o = 16; o; o >>= 1) m = fmaxf(m, __shfl_xor_sync(0xffffffffu, m, o));
    if ((threadIdx.x & 31) == 0) atomicMax(&g_absmax[which], __float_as_uint(m));
}
// merged quantization + conv transpose
__global__ void prep_k(const float* __restrict__ spW, const float* __restrict__ fc1W,
                       const float* __restrict__ fc2W, const float* __restrict__ convW) {
    int i = blockIdx.x*blockDim.x + threadIdx.x;
    if (i < N0_) {
        float scale = fmaxf(__fdiv_rn(__uint_as_float(g_absmax[0]), 7.0f), 1e-8f);
        g_qsp[i] = __fmul_rn(rintf(__fdiv_rn(spW[i], scale)), scale);
    } else if (i < N0_ + N1_) {
        int j = i - N0_;
        float scale = fmaxf(__fdiv_rn(__uint_as_float(g_absmax[1]), 7.0f), 1e-8f);
        float k = rintf(__fdiv_rn(fc1W[j], scale));
        g_qfc1[j] = __fmul_rn(k, scale);
        g_qk[j]   = k;
    } else if (i < N0_ + N1_ + N2_) {
        int j = i - N0_ - N1_;
        float scale = fmaxf(__fdiv_rn(__uint_as_float(g_absmax[2]), 7.0f), 1e-8f);
        g_qfc2[j] = __fmul_rn(rintf(__fdiv_rn(fc2W[j], scale)), scale);
    } else {
        int j = i - N0_ - N1_ - N2_;
        int o = j / KC_, rem = j % KC_;
        int k = rem >> 8, c = rem & 255;
        g_convWt[j] = convW[o*KC_ + c*5 + k];
    }
}

// ---------------- FFMA2 double-buffered SGEMM 64x128x16 (exact fp32) -----------------
// 256 threads = 8 warps in 2(M)x4(N) of 32x32 warp tiles, per-thread 4x8, 2 CTAs/SM.
template<int CONV>
__device__ __forceinline__ float4 ldA(const float* __restrict__ A, int K, int row, int c) {
    if (CONV) {
        int tap = c >> 8, chn = c & 255;
        int b = row / T_, t = row - b*T_;
        int ts = t + tap - 2;
        if (ts < 0 || ts >= T_) return make_float4(0,0,0,0);
        return *reinterpret_cast<const float4*>(A + (size_t)(b*T_ + ts)*RED_ + chn);
    } else {
        if (c >= K) return make_float4(0,0,0,0);
        return *reinterpret_cast<const float4*>(A + (size_t)row*K + c);
    }
}

template<int CONV, int SPLIT>
__global__ __launch_bounds__(256, 2)
void sgemm_k(const float* __restrict__ A, const float* __restrict__ B,
             const float* __restrict__ bias, float* __restrict__ C,
             float* __restrict__ Ch, int K, int N)
{
    __shared__ float sA[2][16][64];
    __shared__ float sB[2][16][128];

    const int tid  = threadIdx.x;
    const int lane = tid & 31;
    const int wid  = tid >> 5;
    const int lr   = lane >> 2;          // 0..7
    const int lc   = lane & 3;           // 0..3
    const int wm   = (wid & 1) * 32;     // 2 warps along M
    const int wn   = (wid >> 1) * 32;    // 4 warps along N
    const int bm0  = blockIdx.y * 64, bn0 = blockIdx.x * 128;

    // acc2[in][i][jp]: in = col group (0: wn+lc*4, 1: wn+16+lc*4), i = row, jp = col pair
    unsigned long long acc2[2][4][2];
    #pragma unroll
    for (int in = 0; in < 2; ++in)
        #pragma unroll
        for (int i = 0; i < 4; ++i) {
            acc2[in][i][0] = 0ull;
            acc2[in][i][1] = 0ull;
        }

    const int nch = (K + 15) >> 4;
    float4 va, vb[2];

    {   // prologue chunk 0
        {
            int row = tid >> 2, c = (tid & 3) * 4;
            va = ldA<CONV>(A, K, bm0 + row, c);
        }
        #pragma unroll
        for (int i = 0; i < 2; ++i) {
            int q = tid + 256*i;
            int row = q >> 2, c = (q & 3) * 4;
            vb[i] = (c < K) ? *reinterpret_cast<const float4*>(B + (size_t)(bn0+row)*K + c)
                            : make_float4(0,0,0,0);
        }
        {
            int row = tid >> 2, c4 = (tid & 3) * 4;
            sA[0][c4+0][row] = va.x; sA[0][c4+1][row] = va.y;
            sA[0][c4+2][row] = va.z; sA[0][c4+3][row] = va.w;
        }
        #pragma unroll
        for (int i = 0; i < 2; ++i) {
            int q = tid + 256*i;
            int row = q >> 2, c4 = (q & 3) * 4;
            sB[0][c4+0][row] = vb[i].x; sB[0][c4+1][row] = vb[i].y;
            sB[0][c4+2][row] = vb[i].z; sB[0][c4+3][row] = vb[i].w;
        }
        __syncthreads();
    }

    int p = 0;
    for (int ch = 0; ch < nch; ++ch) {
        const bool more = (ch + 1 < nch);
        if (more) {
            int k0 = (ch + 1) * 16;
            {
                int row = tid >> 2, c = k0 + (tid & 3) * 4;
                va = ldA<CONV>(A, K, bm0 + row, c);
            }
            #pragma unroll
            for (int i = 0; i < 2; ++i) {
                int q = tid + 256*i;
                int row = q >> 2, c = k0 + (q & 3) * 4;
                vb[i] = (c < K) ? *reinterpret_cast<const float4*>(B + (size_t)(bn0+row)*K + c)
                                : make_float4(0,0,0,0);
            }
        }
        #pragma unroll
        for (int kk = 0; kk < 16; ++kk) {
            float4 a0 = *reinterpret_cast<const float4*>(&sA[p][kk][wm + lr*4]);
            ulonglong2 b0 = *reinterpret_cast<const ulonglong2*>(&sB[p][kk][wn + lc*4]);
            ulonglong2 b1 = *reinterpret_cast<const ulonglong2*>(&sB[p][kk][wn + 16 + lc*4]);
            unsigned long long bp[2][2] = { { b0.x, b0.y }, { b1.x, b1.y } };
            const float av[4] = { a0.x, a0.y, a0.z, a0.w };
            #pragma unroll
            for (int i = 0; i < 4; ++i) {
                unsigned long long ad = dup_f32x2(av[i]);
                #pragma unroll
                for (int in = 0; in < 2; ++in) {
                    ffma2(acc2[in][i][0], ad, bp[in][0]);
                    ffma2(acc2[in][i][1], ad, bp[in][1]);
                }
            }
        }
        if (more) {
            int q2 = p ^ 1;
            {
                int row = tid >> 2, c4 = (tid & 3) * 4;
                sA[q2][c4+0][row] = va.x; sA[q2][c4+1][row] = va.y;
                sA[q2][c4+2][row] = va.z; sA[q2][c4+3][row] = va.w;
            }
            #pragma unroll
            for (int i = 0; i < 2; ++i) {
                int q = tid + 256*i;
                int row = q >> 2, c4 = (q & 3) * 4;
                sB[q2][c4+0][row] = vb[i].x; sB[q2][c4+1][row] = vb[i].y;
                sB[q2][c4+2][row] = vb[i].z; sB[q2][c4+3][row] = vb[i].w;
            }
            __syncthreads();
            p = q2;
        }
    }

    #pragma unroll
    for (int i = 0; i < 4; ++i) {
        int row = bm0 + wm + lr*4 + i;
        #pragma unroll
        for (int in = 0; in < 2; ++in) {
            int col = bn0 + wn + in*16 + lc*4;
            float2 p01 = unpack_f32x2(acc2[in][i][0]);
            float2 p23 = unpack_f32x2(acc2[in][i][1]);
            float4 v;
            v.x = fmaxf(p01.x + __ldg(bias + col + 0), 0.0f);
            v.y = fmaxf(p01.y + __ldg(bias + col + 1), 0.0f);
            v.z = fmaxf(p23.x + __ldg(bias + col + 2), 0.0f);
            v.w = fmaxf(p23.y + __ldg(bias + col + 3), 0.0f);
            *reinterpret_cast<float4*>(C + (size_t)row*N + col) = v;
            if (SPLIT) {
                float4 hv;
                hv.x = tf32_hi(v.x); hv.y = tf32_hi(v.y);
                hv.z = tf32_hi(v.z); hv.w = tf32_hi(v.w);
                *reinterpret_cast<float4*>(Ch + (size_t)row*N + col) = hv;
            }
        }
    }
}

// ---------------- GEMM2: 1-pass tf32 (A = tf32(co), B = int4 levels) ------------------
#define AST 20
#define ASZ (128*AST)
#define BSZ (64*AST)
#define G2_SMEM ((2*ASZ + 2*BSZ)*4)     // 30720 B

__device__ __forceinline__ void g2_issue(const float* __restrict__ coh,
                                         const float* __restrict__ qk,
                                         uint32_t sAa, uint32_t sBa,
                                         int bm0, int bn0, int k0, int tid) {
    #pragma unroll
    for (int i = 0; i < 2; ++i) {
        int cid = tid + 256*i;
        int row = cid >> 2, kq = (cid & 3) * 4;
        const float* g = coh + (size_t)(bm0+row)*RED_ + k0 + kq;
        CP_ASYNC16(sAa + (uint32_t)((row*AST + kq) * 4), g);
    }
    {
        int row = tid >> 2, kq = (tid & 3) * 4;
        const float* g = qk + (size_t)(bn0+row)*RED_ + k0 + kq;
        CP_ASYNC16(sBa + (uint32_t)((row*AST + kq) * 4), g);
    }
    CP_COMMIT();
}

__global__ __launch_bounds__(256, 3)
void g2tf_k(const float* __restrict__ coh, const float* __restrict__ qk,
            const float* __restrict__ bias,
            const float* __restrict__ latent, const float* __restrict__ gainp,
            float* __restrict__ drv, float* __restrict__ spk)
{
    extern __shared__ float smf[];
    const uint32_t smem_base = smem_u32(smf);
    float* smB = smf + 2*ASZ;

    const int tid  = threadIdx.x;
    const int lane = tid & 31;
    const int wid  = tid >> 5;
    const int wm   = (wid & 3) * 32;
    const int wn   = (wid >> 2) * 32;
    const int bm0  = blockIdx.y * 128, bn0 = blockIdx.x * 64;

    float acc[2][4][4];
    #pragma unroll
    for (int mi = 0; mi < 2; ++mi)
        #pragma unroll
        for (int ni = 0; ni < 4; ++ni)
            #pragma unroll
            for (int q = 0; q < 4; ++q) acc[mi][ni][q] = 0.0f;

    g2_issue(coh, qk, smem_base, smem_base + 2*ASZ*4, bm0, bn0, 0, tid);

    #pragma unroll 1
    for (int ch = 0; ch < 16; ++ch) {
        CP_WAIT0();
        __syncthreads();
        const int p = ch & 1;
        if (ch + 1 < 16) {
            const int q2 = p ^ 1;
            g2_issue(coh, qk, smem_base + q2*ASZ*4,
                     smem_base + (2*ASZ + q2*BSZ)*4, bm0, bn0, (ch+1)*16, tid);
        }
        const float* A2 = smf + p*ASZ;
        const float* B2 = smB + p*BSZ;
        #pragma unroll
        for (int ksl = 0; ksl < 2; ++ksl) {
            const int bc = ksl*8 + (lane & 3);
            float afr[2][4];
            #pragma unroll
            for (int mi = 0; mi < 2; ++mi) {
                int r = wm + (lane >> 2) + mi*16;
                afr[mi][0] = A2[r*AST + bc];
                afr[mi][1] = A2[(r+8)*AST + bc];
                afr[mi][2] = A2[r*AST + bc + 4];
                afr[mi][3] = A2[(r+8)*AST + bc + 4];
            }
            float bfr[4][2];
            #pragma unroll
            for (int ni = 0; ni < 4; ++ni) {
                int n = wn + ni*8 + (lane >> 2);
                bfr[ni][0] = B2[n*AST + bc];
                bfr[ni][1] = B2[n*AST + bc + 4];
            }
            #pragma unroll
            for (int mi = 0; mi < 2; ++mi)
                #pragma unroll
                for (int ni = 0; ni < 4; ++ni)
                    MMA_TF32(acc[mi][ni], afr[mi], bfr[ni]);
        }
    }

    const int r0 = bm0 + wm + (lane >> 2);
    const int c0 = bn0 + wn + (lane & 3)*2;
    const float gabs = fabsf(gainp[0]);
    const float scaleB = fmaxf(__fdiv_rn(__uint_as_float(g_absmax[1]), 7.0f), 1e-8f);

    #pragma unroll
    for (int mi = 0; mi < 2; ++mi)
        #pragma unroll
        for (int ni = 0; ni < 4; ++ni) {
            int col = c0 + ni*8;
            float b0 = __ldg(bias + col), b1 = __ldg(bias + col + 1);
            #pragma unroll
            for (int h = 0; h < 2; ++h) {
                int row = r0 + mi*16 + h*8;
                float lat = __ldg(latent + (row % T_));
                float2 dv, sv;
                #pragma unroll
                for (int q = 0; q < 2; ++q) {
                    float pre = fmaf(acc[mi][ni][h*2+q], scaleB, q ? b1 : b0);
                    float e   = __expf(-fabsf(pre));
                    float sp  = fmaxf(pre, 0.0f) + __logf(1.0f + e);
                    float d   = (sp * lat) * gabs;
                    unsigned idx = (unsigned)row * (unsigned)WID_ + (unsigned)(col + q);
                    unsigned bits = rbits32(idx);
                    float u = __uint_as_float((bits >> 9) | 0x3f800000u) - 1.0f;
                    float spike;
                    if (d >= 10.0f) spike = 1.0f;
                    else {
                        float t = __expf(-d);
                        spike = (u > t) ? 1.0f : 0.0f;
                        if (fabsf(u - t) < MARGIN * t) {
                            unsigned w = atomicAdd(&g_count, 1u);
                            if (w < WCAP) g_worklist[w] = idx;
                        }
                    }
                    if (q) { dv.y = d; sv.y = spike; } else { dv.x = d; sv.x = spike; }
                }
                size_t ob = (size_t)row * WID_ + col;
                *reinterpret_cast<float2*>(drv + ob) = dv;
                *reinterpret_cast<float2*>(spk + ob) = sv;
            }
        }
}

// ---------------- exact fp32 fixup for borderline spikes (reference semantics) --------
__global__ void fixup_k(const float* __restrict__ co, const float* __restrict__ qfc1,
                        const float* __restrict__ bias, const float* __restrict__ latent,
                        const float* __restrict__ gainp, float* __restrict__ spk)
{
    __shared__ float red[4];
    const unsigned n = (g_count < WCAP) ? g_count : WCAP;
    const float gabs = fabsf(gainp[0]);
    const int tid = threadIdx.x;   // 128
    for (unsigned i = blockIdx.x; i < n; i += gridDim.x) {
        unsigned idx = g_worklist[i];
        int row = idx >> 12, col = idx & (WID_-1);
        const float* cr = co + (size_t)row * RED_;
        const float* wr = qfc1 + (size_t)col * RED_;
        float s = cr[tid]*wr[tid] + cr[tid+128]*wr[tid+128];
        #pragma unroll
        for (int o = 16; o; o >>= 1) s += __shfl_xor_sync(0xffffffffu, s, o);
        if ((tid & 31) == 0) red[tid >> 5] = s;
        __syncthreads();
        if (tid == 0) {
            float pre = (red[0]+red[1]) + (red[2]+red[3]) + bias[col];
            float spl = fmaxf(pre, 0.0f) + log1pf(expf(-fabsf(pre)));
            float d   = (spl * latent[row % T_]) * gabs;
            unsigned bits = rbits32(idx);
            float u = __uint_as_float((bits >> 9) | 0x3f800000u) - 1.0f;
            spk[idx] = (d >= 10.0f) ? 1.0f : ((logf(u) > -d) ? 1.0f : 0.0f);
        }
        __syncthreads();
    }
}

// ---------------- decay-weighted temporal reduction (latency-optimized) ---------------
__global__ void weighted_k(const float* __restrict__ spikes) {
    int idx = blockIdx.x * blockDim.x + threadIdx.x;
    if (idx >= B_*WID_) return;
    int b = idx >> 12, w = idx & (WID_-1);
    const float* sp = spikes + (size_t)b*T_*WID_ + w;
    float s0 = 0.0f, s1 = 0.0f, s2 = 0.0f, s3 = 0.0f;
    #pragma unroll
    for (int t = 0; t < T_; t += 4) {
        s0 = fmaf(__ldg(sp + (size_t)(t+0)*WID_), g_decay[t+0], s0);
        s1 = fmaf(__ldg(sp + (size_t)(t+1)*WID_), g_decay[t+1], s1);
        s2 = fmaf(__ldg(sp + (size_t)(t+2)*WID_), g_decay[t+2], s2);
        s3 = fmaf(__ldg(sp + (size_t)(t+3)*WID_), g_decay[t+3], s3);
    }
    g_wsum[idx] = (s0 + s1) + (s2 + s3);
}

// ---------------- logits ----------------
__global__ void logits_k(const float* __restrict__ bias, float* __restrict__ out) {
    int bc = blockIdx.x;
    int b = bc / CLS_, c = bc % CLS_;
    const float* wr = g_wsum + (size_t)b*WID_;
    const float* fr = g_qfc2 + (size_t)c*WID_;
    float s = 0.0f;
    for (int i = threadIdx.x; i < WID_; i += 128) s += wr[i]*fr[i];
    #pragma unroll
    for (int o = 16; o; o >>= 1) s += __shfl_xor_sync(0xffffffffu, s, o);
    __shared__ float red[4];
    if ((threadIdx.x & 31) == 0) red[threadIdx.x >> 5] = s;
    __syncthreads();
    if (threadIdx.x == 0) out[bc] = (red[0]+red[1]+red[2]+red[3]) + bias[c];
}

// ---------------- launcher ----------------
extern "C" void kernel_launch(void* const* d_in, const int* in_sizes, int n_in,
                              void* d_out, int out_size) {
    (void)in_sizes; (void)n_in; (void)out_size;
    const float* x        = (const float*)d_in[0];
    const float* latent   = (const float*)d_in[1];
    const float* spatialW = (const float*)d_in[2];
    const float* spatialB = (const float*)d_in[3];
    const float* convW    = (const float*)d_in[4];
    const float* convB    = (const float*)d_in[5];
    const float* fc1W     = (const float*)d_in[6];
    const float* fc1B     = (const float*)d_in[7];
    const float* fc2W     = (const float*)d_in[8];
    const float* fc2B     = (const float*)d_in[9];
    const float* gain     = (const float*)d_in[10];

    float* out        = (float*)d_out;
    float* out_logits = out;
    float* out_spk    = out + (CLS_*B_);
    float* out_drv    = out + (CLS_*B_) + (size_t)NELEM_;

    float *qsp, *qfc1, *qk, *qfc2, *cwt, *xp, *co, *coh;
    cudaGetSymbolAddress((void**)&qsp,  g_qsp);
    cudaGetSymbolAddress((void**)&qfc1, g_qfc1);
    cudaGetSymbolAddress((void**)&qk,   g_qk);
    cudaGetSymbolAddress((void**)&qfc2, g_qfc2);
    cudaGetSymbolAddress((void**)&cwt,  g_convWt);
    cudaGetSymbolAddress((void**)&xp,   g_xp);
    cudaGetSymbolAddress((void**)&co,   g_co);
    cudaGetSymbolAddress((void**)&coh,  g_coh);

    static bool attr_set = false;
    if (!attr_set) {
        cudaFuncSetAttribute(g2tf_k, cudaFuncAttributeMaxDynamicSharedMemorySize, G2_SMEM);
        attr_set = true;
    }

    init_k<<<1, 128>>>();
    absmax3_k<<<384, 256>>>(spatialW, fc1W, fc2W);
    prep_k<<<NPREP_/256, 256>>>(spatialW, fc1W, fc2W, convW);

    // GEMM1: xp = relu(x @ qsp^T + b)   (exact fp32 FFMA2, grid 2x100 = 200 CTAs)
    sgemm_k<0,0><<<dim3(RED_/128, ROWS_/64), 256>>>(x, qsp, spatialB, xp, nullptr, INF_, RED_);
    // conv (fused im2col): co = relu(im2col(xp) @ cwt^T + cb), also emits coh = tf32(co)
    sgemm_k<1,1><<<dim3(RED_/128, ROWS_/64), 256>>>(xp, cwt, convB, co, coh, KC_, RED_);
    // GEMM2 (tf32 1-pass, int4-level B, scale factored) + drive/spike + flags
    g2tf_k<<<dim3(WID_/64, ROWS_/128), 256, G2_SMEM>>>(coh, qk, fc1B,
                                                       latent, gain, out_drv, out_spk);
    // exact recompute of borderline spikes
    fixup_k<<<2048, 128>>>(co, qfc1, fc1B, latent, gain, out_spk);
    weighted_k<<<(B_*WID_ + 255)/256, 256>>>(out_spk);
    logits_k<<<B_*CLS_, 128>>>(fc2B, out_logits);
}

// round 15
// speedup vs baseline: 1.2799x; 1.1170x over previous
#include <cuda_runtime.h>
#include <cstdint>

// ---------------- problem dims ----------------
#define B_    64
#define T_    100
#define INF_  700
#define RED_  256
#define WID_  4096
#define CLS_  20
#define ROWS_ (B_*T_)          // 6400
#define KC_   1280             // conv im2col K (256*5)
#define NELEM_ (ROWS_*WID_)    // 26214400
#define WCAP  (1u<<22)
#define MARGIN 2.5e-3f

#define N0_ (RED_*INF_)        // 179200
#define N1_ (WID_*RED_)        // 1048576
#define N2_ (CLS_*WID_)        // 81920
#define N3_ (RED_*KC_)         // 327680
#define NPREP_ (N0_+N1_+N2_+N3_)   // 1637376 = 6396*256

// ---------------- scratch (static device globals; no alloc allowed) ----------------
__device__ unsigned g_absmax[4];
__device__ unsigned g_count;
__device__ unsigned g_worklist[WCAP];
__device__ float  g_decay[T_];
__device__ float  g_qksp[RED_*INF_];      // integer levels of spatial_W (tf32-exact)
__device__ float  g_qfc1[WID_*RED_];      // exact scale*k (fixup)
__device__ float  g_qk[WID_*RED_];        // integer k of fc1 (tf32-exact)
__device__ float  g_qfc2[CLS_*WID_];
__device__ float  g_convWt[RED_*KC_];
__device__ float  g_xp[ROWS_*RED_];
__device__ float  g_co[ROWS_*RED_];       // exact (fixup)
__device__ float  g_coh[ROWS_*RED_];      // tf32 hi of co
__device__ float  g_wsum[B_*WID_];

// ---------------- threefry2x32 (JAX-compatible, partitionable mode) ----------------
__host__ __device__ constexpr unsigned rotl32c(unsigned v, int s) {
    return (v << s) | (v >> (32 - s));
}
struct K2 { unsigned a, b; };
constexpr K2 tf_const(unsigned k0, unsigned k1, unsigned x0, unsigned x1) {
    unsigned ks2 = k0 ^ k1 ^ 0x1BD11BDAu;
    unsigned ks[3] = {k0, k1, ks2};
    x0 += k0; x1 += k1;
    const int R[20] = {13,15,26,6, 17,29,16,24, 13,15,26,6, 17,29,16,24, 13,15,26,6};
    for (int g = 0; g < 5; ++g) {
        for (int j = 0; j < 4; ++j) { x0 += x1; x1 = rotl32c(x1, R[g*4+j]); x1 ^= x0; }
        x0 += ks[(g+1)%3];
        x1 += ks[(g+2)%3] + (unsigned)(g+1);
    }
    return K2{x0, x1};
}
constexpr K2 SUBKEY = tf_const(0u, 42u, 0u, 1u);
constexpr unsigned SK0 = SUBKEY.a;
constexpr unsigned SK1 = SUBKEY.b;

__device__ __forceinline__ uint2 tf2x32(unsigned k0, unsigned k1, unsigned x0, unsigned x1) {
    unsigned ks2 = k0 ^ k1 ^ 0x1BD11BDAu;
    x0 += k0; x1 += k1;
#define TFR(r) { x0 += x1; x1 = __funnelshift_l(x1, x1, (r)); x1 ^= x0; }
    TFR(13) TFR(15) TFR(26) TFR(6)   x0 += k1;  x1 += ks2 + 1u;
    TFR(17) TFR(29) TFR(16) TFR(24)  x0 += ks2; x1 += k0  + 2u;
    TFR(13) TFR(15) TFR(26) TFR(6)   x0 += k0;  x1 += k1  + 3u;
    TFR(17) TFR(29) TFR(16) TFR(24)  x0 += k1;  x1 += ks2 + 4u;
    TFR(13) TFR(15) TFR(26) TFR(6)   x0 += ks2; x1 += k0  + 5u;
#undef TFR
    return make_uint2(x0, x1);
}
__device__ __forceinline__ unsigned rbits32(unsigned idx) {
    uint2 r = tf2x32(SK0, SK1, 0u, idx);
    return r.x ^ r.y;
}

// ---------------- packed f32x2 helpers ----------------
__device__ __forceinline__ void ffma2(unsigned long long& acc,
                                      unsigned long long a,
                                      unsigned long long b) {
    asm("fma.rn.f32x2 %0, %1, %2, %0;" : "+l"(acc) : "l"(a), "l"(b));
}
__device__ __forceinline__ unsigned long long dup_f32x2(float x) {
    unsigned long long d;
    asm("mov.b64 %0, {%1, %1};" : "=l"(d) : "f"(x));
    return d;
}
__device__ __forceinline__ float2 unpack_f32x2(unsigned long long v) {
    float lo, hi;
    asm("mov.b64 {%0, %1}, %2;" : "=f"(lo), "=f"(hi) : "l"(v));
    return make_float2(lo, hi);
}

// ---------------- tf32 helpers ----------------
__device__ __forceinline__ float tf32_hi(float x) {
    uint32_t u; asm("cvt.rna.tf32.f32 %0, %1;" : "=r"(u) : "f"(x));
    return __uint_as_float(u);
}
#define MMA_TF32(c, a, b) \
    asm volatile("mma.sync.aligned.m16n8k8.row.col.f32.tf32.tf32.f32 " \
        "{%0,%1,%2,%3}, {%4,%5,%6,%7}, {%8,%9}, {%0,%1,%2,%3};" \
        : "+f"((c)[0]), "+f"((c)[1]), "+f"((c)[2]), "+f"((c)[3]) \
        : "r"(__float_as_uint((a)[0])), "r"(__float_as_uint((a)[1])), \
          "r"(__float_as_uint((a)[2])), "r"(__float_as_uint((a)[3])), \
          "r"(__float_as_uint((b)[0])), "r"(__float_as_uint((b)[1])))

__device__ __forceinline__ uint32_t smem_u32(const void* p) {
    uint32_t a;
    asm("{ .reg .u64 t; cvta.to.shared.u64 t, %1; cvt.u32.u64 %0, t; }" : "=r"(a) : "l"(p));
    return a;
}
#define CP_ASYNC16(s, g) \
    asm volatile("cp.async.cg.shared.global [%0], [%1], 16;" :: "r"(s), "l"(g))
#define CP_COMMIT()  asm volatile("cp.async.commit_group;")
#define CP_WAIT0()   asm volatile("cp.async.wait_group 0;")

// ---------------- prep kernels ----------------
__global__ void init_k() {
    if (threadIdx.x < 4) g_absmax[threadIdx.x] = 0u;
    if (threadIdx.x == 0) g_count = 0u;
    if (threadIdx.x < T_)
        g_decay[threadIdx.x] = expf(-2.0f + (float)threadIdx.x * (2.0f/99.0f));
}
// merged absmax over 3 tensors
__global__ void absmax3_k(const float* __restrict__ W0, const float* __restrict__ W1,
                          const float* __restrict__ W2) {
    const float* W; int n, which, b0, nb;
    if (blockIdx.x < 64)        { W = W0; n = N0_; which = 0; b0 = 0;   nb = 64;  }
    else if (blockIdx.x < 320)  { W = W1; n = N1_; which = 1; b0 = 64;  nb = 256; }
    else                        { W = W2; n = N2_; which = 2; b0 = 320; nb = 64;  }
    float m = 0.0f;
    for (int i = (int)(blockIdx.x - b0)*blockDim.x + threadIdx.x; i < n; i += nb*blockDim.x)
        m = fmaxf(m, fabsf(W[i]));
    #pragma unroll
    for (int o = 16; o; o >>= 1) m = fmaxf(m, __shfl_xor_sync(0xffffffffu, m, o));
    if ((threadIdx.x & 31) == 0) atomicMax(&g_absmax[which], __float_as_uint(m));
}
// merged quantization + conv transpose
__global__ void prep_k(const float* __restrict__ spW, const float* __restrict__ fc1W,
                       const float* __restrict__ fc2W, const float* __restrict__ convW) {
    int i = blockIdx.x*blockDim.x + threadIdx.x;
    if (i < N0_) {
        float scale = fmaxf(__fdiv_rn(__uint_as_float(g_absmax[0]), 7.0f), 1e-8f);
        g_qksp[i] = rintf(__fdiv_rn(spW[i], scale));
    } else if (i < N0_ + N1_) {
        int j = i - N0_;
        float scale = fmaxf(__fdiv_rn(__uint_as_float(g_absmax[1]), 7.0f), 1e-8f);
        float k = rintf(__fdiv_rn(fc1W[j], scale));
        g_qfc1[j] = __fmul_rn(k, scale);
        g_qk[j]   = k;
    } else if (i < N0_ + N1_ + N2_) {
        int j = i - N0_ - N1_;
        float scale = fmaxf(__fdiv_rn(__uint_as_float(g_absmax[2]), 7.0f), 1e-8f);
        g_qfc2[j] = __fmul_rn(rintf(__fdiv_rn(fc2W[j], scale)), scale);
    } else {
        int j = i - N0_ - N1_ - N2_;
        int o = j / KC_, rem = j % KC_;
        int k = rem >> 8, c = rem & 255;
        g_convWt[j] = convW[o*KC_ + c*5 + k];
    }
}

// ---------------- GEMM1: 2-pass exact tf32 (A = x hi/lo split, B = int4 levels) ------
// xp = relu(scale0*(x @ k_sp^T) + bias). BM=128, BN=64, BK=16, 44 chunks (K=700).
// Products x_hi*k and x_lo*k are exact (k is 3-bit); x_hi+x_lo = x to 2^-24.
#define G1AST 20
#define G1ASZ (128*G1AST)
#define G1BSZ (64*G1AST)
#define G1_SMEM ((2*2*G1ASZ + 2*G1BSZ)*4)   // (10240+2560)*4 = 51200 B

__global__ __launch_bounds__(256, 2)
void g1tf_k(const float* __restrict__ x, const float* __restrict__ qksp,
            const float* __restrict__ bias, float* __restrict__ xp)
{
    extern __shared__ float smf[];
    float* sAh = smf;                       // [2][G1ASZ]
    float* sAl = smf + 2*G1ASZ;             // [2][G1ASZ]
    float* sBp = smf + 4*G1ASZ;             // [2][G1BSZ]

    const int tid  = threadIdx.x;
    const int lane = tid & 31;
    const int wid  = tid >> 5;
    const int wm   = (wid & 3) * 32;        // 4 warps along M
    const int wn   = (wid >> 2) * 32;       // 2 warps along N
    const int bm0  = blockIdx.y * 128, bn0 = blockIdx.x * 64;
    const int K = INF_;                     // 700
    const int nch = (K + 15) >> 4;          // 44

    float acc[2][4][4];
    #pragma unroll
    for (int mi = 0; mi < 2; ++mi)
        #pragma unroll
        for (int ni = 0; ni < 4; ++ni)
            #pragma unroll
            for (int q = 0; q < 4; ++q) acc[mi][ni][q] = 0.0f;

    float4 va[2], vb;
    // prologue chunk 0
    {
        #pragma unroll
        for (int i = 0; i < 2; ++i) {
            int q = tid + 256*i;
            int row = q >> 2, c = (q & 3) * 4;
            va[i] = (c < K) ? *reinterpret_cast<const float4*>(x + (size_t)(bm0+row)*K + c)
                            : make_float4(0,0,0,0);
        }
        {
            int row = tid >> 2, c = (tid & 3) * 4;
            vb = (c < K) ? *reinterpret_cast<const float4*>(qksp + (size_t)(bn0+row)*K + c)
                         : make_float4(0,0,0,0);
        }
        #pragma unroll
        for (int i = 0; i < 2; ++i) {
            int q = tid + 256*i;
            int row = q >> 2, c4 = (q & 3) * 4;
            float4 h, l;
            h.x = tf32_hi(va[i].x); l.x = tf32_hi(va[i].x - h.x);
            h.y = tf32_hi(va[i].y); l.y = tf32_hi(va[i].y - h.y);
            h.z = tf32_hi(va[i].z); l.z = tf32_hi(va[i].z - h.z);
            h.w = tf32_hi(va[i].w); l.w = tf32_hi(va[i].w - h.w);
            *reinterpret_cast<float4*>(sAh + row*G1AST + c4) = h;
            *reinterpret_cast<float4*>(sAl + row*G1AST + c4) = l;
        }
        {
            int row = tid >> 2, c4 = (tid & 3) * 4;
            *reinterpret_cast<float4*>(sBp + row*G1AST + c4) = vb;
        }
        __syncthreads();
    }

    int p = 0;
    for (int ch = 0; ch < nch; ++ch) {
        const bool more = (ch + 1 < nch);
        if (more) {
            int k0 = (ch + 1) * 16;
            #pragma unroll
            for (int i = 0; i < 2; ++i) {
                int q = tid + 256*i;
                int row = q >> 2, c = k0 + (q & 3) * 4;
                va[i] = (c < K) ? *reinterpret_cast<const float4*>(x + (size_t)(bm0+row)*K + c)
                                : make_float4(0,0,0,0);
            }
            {
                int row = tid >> 2, c = k0 + (tid & 3) * 4;
                vb = (c < K) ? *reinterpret_cast<const float4*>(qksp + (size_t)(bn0+row)*K + c)
                             : make_float4(0,0,0,0);
            }
        }
        const float* Ah = sAh + p*G1ASZ;
        const float* Al = sAl + p*G1ASZ;
        const float* Bp = sBp + p*G1BSZ;
        #pragma unroll
        for (int ksl = 0; ksl < 2; ++ksl) {
            const int bc = ksl*8 + (lane & 3);
            float ah[2][4], al[2][4];
            #pragma unroll
            for (int mi = 0; mi < 2; ++mi) {
                int r = wm + (lane >> 2) + mi*16;
                ah[mi][0] = Ah[r*G1AST + bc];
                ah[mi][1] = Ah[(r+8)*G1AST + bc];
                ah[mi][2] = Ah[r*G1AST + bc + 4];
                ah[mi][3] = Ah[(r+8)*G1AST + bc + 4];
                al[mi][0] = Al[r*G1AST + bc];
                al[mi][1] = Al[(r+8)*G1AST + bc];
                al[mi][2] = Al[r*G1AST + bc + 4];
                al[mi][3] = Al[(r+8)*G1AST + bc + 4];
            }
            float bfr[4][2];
            #pragma unroll
            for (int ni = 0; ni < 4; ++ni) {
                int n = wn + ni*8 + (lane >> 2);
                bfr[ni][0] = Bp[n*G1AST + bc];
                bfr[ni][1] = Bp[n*G1AST + bc + 4];
            }
            #pragma unroll
            for (int mi = 0; mi < 2; ++mi)
                #pragma unroll
                for (int ni = 0; ni < 4; ++ni) {
                    MMA_TF32(acc[mi][ni], ah[mi], bfr[ni]);
                    MMA_TF32(acc[mi][ni], al[mi], bfr[ni]);
                }
        }
        if (more) {
            int q2 = p ^ 1;
            float* Ah2 = sAh + q2*G1ASZ;
            float* Al2 = sAl + q2*G1ASZ;
            float* Bp2 = sBp + q2*G1BSZ;
            #pragma unroll
            for (int i = 0; i < 2; ++i) {
                int q = tid + 256*i;
                int row = q >> 2, c4 = (q & 3) * 4;
                float4 h, l;
                h.x = tf32_hi(va[i].x); l.x = tf32_hi(va[i].x - h.x);
                h.y = tf32_hi(va[i].y); l.y = tf32_hi(va[i].y - h.y);
                h.z = tf32_hi(va[i].z); l.z = tf32_hi(va[i].z - h.z);
                h.w = tf32_hi(va[i].w); l.w = tf32_hi(va[i].w - h.w);
                *reinterpret_cast<float4*>(Ah2 + row*G1AST + c4) = h;
                *reinterpret_cast<float4*>(Al2 + row*G1AST + c4) = l;
            }
            {
                int row = tid >> 2, c4 = (tid & 3) * 4;
                *reinterpret_cast<float4*>(Bp2 + row*G1AST + c4) = vb;
            }
            __syncthreads();
            p = q2;
        }
    }

    // epilogue: xp = relu(acc*scale0 + bias)
    const int r0 = bm0 + wm + (lane >> 2);
    const int c0 = bn0 + wn + (lane & 3)*2;
    const float scale0 = fmaxf(__fdiv_rn(__uint_as_float(g_absmax[0]), 7.0f), 1e-8f);

    #pragma unroll
    for (int mi = 0; mi < 2; ++mi)
        #pragma unroll
        for (int ni = 0; ni < 4; ++ni) {
            int col = c0 + ni*8;
            float b0 = __ldg(bias + col), b1 = __ldg(bias + col + 1);
            #pragma unroll
            for (int h = 0; h < 2; ++h) {
                int row = r0 + mi*16 + h*8;
                float2 v;
                v.x = fmaxf(fmaf(acc[mi][ni][h*2+0], scale0, b0), 0.0f);
                v.y = fmaxf(fmaf(acc[mi][ni][h*2+1], scale0, b1), 0.0f);
                *reinterpret_cast<float2*>(xp + (size_t)row*RED_ + col) = v;
            }
        }
}

// ---------------- conv: FFMA2 double-buffered SGEMM 128x128x16 (exact fp32) ----------
__device__ __forceinline__ float4 ldA_conv(const float* __restrict__ A, int row, int c) {
    int tap = c >> 8, chn = c & 255;
    int b = row / T_, t = row - b*T_;
    int ts = t + tap - 2;
    if (ts < 0 || ts >= T_) return make_float4(0,0,0,0);
    return *reinterpret_cast<const float4*>(A + (size_t)(b*T_ + ts)*RED_ + chn);
}

__global__ __launch_bounds__(256, 2)
void conv_k(const float* __restrict__ A, const float* __restrict__ B,
            const float* __restrict__ bias, float* __restrict__ C,
            float* __restrict__ Ch)
{
    __shared__ float sA[2][16][128];
    __shared__ float sB[2][16][128];

    const int K = KC_, N = RED_;
    const int tid  = threadIdx.x;
    const int lane = tid & 31;
    const int wid  = tid >> 5;
    const int lr   = lane >> 2;
    const int lc   = lane & 3;
    const int wm   = (wid & 1) * 64;
    const int wn   = (wid >> 1) * 32;
    const int bm0  = blockIdx.y * 128, bn0 = blockIdx.x * 128;

    unsigned long long acc2[2][2][4][2];
    #pragma unroll
    for (int im = 0; im < 2; ++im)
        #pragma unroll
        for (int in = 0; in < 2; ++in)
            #pragma unroll
            for (int i = 0; i < 4; ++i) {
                acc2[im][in][i][0] = 0ull;
                acc2[im][in][i][1] = 0ull;
            }

    const int nch = (K + 15) >> 4;
    float4 va[2], vb[2];

    {
        #pragma unroll
        for (int i = 0; i < 2; ++i) {
            int q = tid + 256*i;
            int row = q >> 2, c = (q & 3) * 4;
            va[i] = ldA_conv(A, bm0 + row, c);
            vb[i] = *reinterpret_cast<const float4*>(B + (size_t)(bn0+row)*K + c);
        }
        #pragma unroll
        for (int i = 0; i < 2; ++i) {
            int q = tid + 256*i;
            int row = q >> 2, c4 = (q & 3) * 4;
            sA[0][c4+0][row] = va[i].x; sA[0][c4+1][row] = va[i].y;
            sA[0][c4+2][row] = va[i].z; sA[0][c4+3][row] = va[i].w;
            sB[0][c4+0][row] = vb[i].x; sB[0][c4+1][row] = vb[i].y;
            sB[0][c4+2][row] = vb[i].z; sB[0][c4+3][row] = vb[i].w;
        }
        __syncthreads();
    }

    int p = 0;
    for (int ch = 0; ch < nch; ++ch) {
        const bool more = (ch + 1 < nch);
        if (more) {
            int k0 = (ch + 1) * 16;
            #pragma unroll
            for (int i = 0; i < 2; ++i) {
                int q = tid + 256*i;
                int row = q >> 2, c = k0 + (q & 3) * 4;
                va[i] = ldA_conv(A, bm0 + row, c);
                vb[i] = *reinterpret_cast<const float4*>(B + (size_t)(bn0+row)*K + c);
            }
        }
        #pragma unroll
        for (int kk = 0; kk < 16; ++kk) {
            float4 a0 = *reinterpret_cast<const float4*>(&sA[p][kk][wm + lr*4]);
            float4 a1 = *reinterpret_cast<const float4*>(&sA[p][kk][wm + 32 + lr*4]);
            ulonglong2 b0 = *reinterpret_cast<const ulonglong2*>(&sB[p][kk][wn + lc*4]);
            ulonglong2 b1 = *reinterpret_cast<const ulonglong2*>(&sB[p][kk][wn + 16 + lc*4]);
            unsigned long long bp[2][2] = { { b0.x, b0.y }, { b1.x, b1.y } };
            const float av[2][4] = { { a0.x, a0.y, a0.z, a0.w },
                                     { a1.x, a1.y, a1.z, a1.w } };
            #pragma unroll
            for (int im = 0; im < 2; ++im)
                #pragma unroll
                for (int i = 0; i < 4; ++i) {
                    unsigned long long ad = dup_f32x2(av[im][i]);
                    #pragma unroll
                    for (int in = 0; in < 2; ++in) {
                        ffma2(acc2[im][in][i][0], ad, bp[in][0]);
                        ffma2(acc2[im][in][i][1], ad, bp[in][1]);
                    }
                }
        }
        if (more) {
            int q2 = p ^ 1;
            #pragma unroll
            for (int i = 0; i < 2; ++i) {
                int q = tid + 256*i;
                int row = q >> 2, c4 = (q & 3) * 4;
                sA[q2][c4+0][row] = va[i].x; sA[q2][c4+1][row] = va[i].y;
                sA[q2][c4+2][row] = va[i].z; sA[q2][c4+3][row] = va[i].w;
                sB[q2][c4+0][row] = vb[i].x; sB[q2][c4+1][row] = vb[i].y;
                sB[q2][c4+2][row] = vb[i].z; sB[q2][c4+3][row] = vb[i].w;
            }
            __syncthreads();
            p = q2;
        }
    }

    #pragma unroll
    for (int im = 0; im < 2; ++im)
        #pragma unroll
        for (int i = 0; i < 4; ++i) {
            int row = bm0 + wm + im*32 + lr*4 + i;
            #pragma unroll
            for (int in = 0; in < 2; ++in) {
                int col = bn0 + wn + in*16 + lc*4;
                float2 p01 = unpack_f32x2(acc2[im][in][i][0]);
                float2 p23 = unpack_f32x2(acc2[im][in][i][1]);
                float4 v;
                v.x = fmaxf(p01.x + __ldg(bias + col + 0), 0.0f);
                v.y = fmaxf(p01.y + __ldg(bias + col + 1), 0.0f);
                v.z = fmaxf(p23.x + __ldg(bias + col + 2), 0.0f);
                v.w = fmaxf(p23.y + __ldg(bias + col + 3), 0.0f);
                *reinterpret_cast<float4*>(C + (size_t)row*N + col) = v;
                float4 hv;
                hv.x = tf32_hi(v.x); hv.y = tf32_hi(v.y);
                hv.z = tf32_hi(v.z); hv.w = tf32_hi(v.w);
                *reinterpret_cast<float4*>(Ch + (size_t)row*N + col) = hv;
            }
        }
}

// ---------------- GEMM2: 1-pass tf32 (A = tf32(co), B = int4 levels) ------------------
#define AST 20
#define ASZ (128*AST)
#define BSZ (64*AST)
#define G2_SMEM ((2*ASZ + 2*BSZ)*4)     // 30720 B

__device__ __forceinline__ void g2_issue(const float* __restrict__ coh,
                                         const float* __restrict__ qk,
                                         uint32_t sAa, uint32_t sBa,
                                         int bm0, int bn0, int k0, int tid) {
    #pragma unroll
    for (int i = 0; i < 2; ++i) {
        int cid = tid + 256*i;
        int row = cid >> 2, kq = (cid & 3) * 4;
        const float* g = coh + (size_t)(bm0+row)*RED_ + k0 + kq;
        CP_ASYNC16(sAa + (uint32_t)((row*AST + kq) * 4), g);
    }
    {
        int row = tid >> 2, kq = (tid & 3) * 4;
        const float* g = qk + (size_t)(bn0+row)*RED_ + k0 + kq;
        CP_ASYNC16(sBa + (uint32_t)((row*AST + kq) * 4), g);
    }
    CP_COMMIT();
}

__global__ __launch_bounds__(256, 3)
void g2tf_k(const float* __restrict__ coh, const float* __restrict__ qk,
            const float* __restrict__ bias,
            const float* __restrict__ latent, const float* __restrict__ gainp,
            float* __restrict__ drv, float* __restrict__ spk)
{
    extern __shared__ float smf[];
    const uint32_t smem_base = smem_u32(smf);
    float* smB = smf + 2*ASZ;

    const int tid  = threadIdx.x;
    const int lane = tid & 31;
    const int wid  = tid >> 5;
    const int wm   = (wid & 3) * 32;
    const int wn   = (wid >> 2) * 32;
    const int bm0  = blockIdx.y * 128, bn0 = blockIdx.x * 64;

    float acc[2][4][4];
    #pragma unroll
    for (int mi = 0; mi < 2; ++mi)
        #pragma unroll
        for (int ni = 0; ni < 4; ++ni)
            #pragma unroll
            for (int q = 0; q < 4; ++q) acc[mi][ni][q] = 0.0f;

    g2_issue(coh, qk, smem_base, smem_base + 2*ASZ*4, bm0, bn0, 0, tid);

    #pragma unroll 1
    for (int ch = 0; ch < 16; ++ch) {
        CP_WAIT0();
        __syncthreads();
        const int p = ch & 1;
        if (ch + 1 < 16) {
            const int q2 = p ^ 1;
            g2_issue(coh, qk, smem_base + q2*ASZ*4,
                     smem_base + (2*ASZ + q2*BSZ)*4, bm0, bn0, (ch+1)*16, tid);
        }
        const float* A2 = smf + p*ASZ;
        const float* B2 = smB + p*BSZ;
        #pragma unroll
        for (int ksl = 0; ksl < 2; ++ksl) {
            const int bc = ksl*8 + (lane & 3);
            float afr[2][4];
            #pragma unroll
            for (int mi = 0; mi < 2; ++mi) {
                int r = wm + (lane >> 2) + mi*16;
                afr[mi][0] = A2[r*AST + bc];
                afr[mi][1] = A2[(r+8)*AST + bc];
                afr[mi][2] = A2[r*AST + bc + 4];
                afr[mi][3] = A2[(r+8)*AST + bc + 4];
            }
            float bfr[4][2];
            #pragma unroll
            for (int ni = 0; ni < 4; ++ni) {
                int n = wn + ni*8 + (lane >> 2);
                bfr[ni][0] = B2[n*AST + bc];
                bfr[ni][1] = B2[n*AST + bc + 4];
            }
            #pragma unroll
            for (int mi = 0; mi < 2; ++mi)
                #pragma unroll
                for (int ni = 0; ni < 4; ++ni)
                    MMA_TF32(acc[mi][ni], afr[mi], bfr[ni]);
        }
    }

    const int r0 = bm0 + wm + (lane >> 2);
    const int c0 = bn0 + wn + (lane & 3)*2;
    const float gabs = fabsf(gainp[0]);
    const float scaleB = fmaxf(__fdiv_rn(__uint_as_float(g_absmax[1]), 7.0f), 1e-8f);

    #pragma unroll
    for (int mi = 0; mi < 2; ++mi)
        #pragma unroll
        for (int ni = 0; ni < 4; ++ni) {
            int col = c0 + ni*8;
            float b0 = __ldg(bias + col), b1 = __ldg(bias + col + 1);
            #pragma unroll
            for (int h = 0; h < 2; ++h) {
                int row = r0 + mi*16 + h*8;
                float lat = __ldg(latent + (row % T_));
                float2 dv, sv;
                #pragma unroll
                for (int q = 0; q < 2; ++q) {
                    float pre = fmaf(acc[mi][ni][h*2+q], scaleB, q ? b1 : b0);
                    float e   = __expf(-fabsf(pre));
                    float sp  = fmaxf(pre, 0.0f) + __logf(1.0f + e);
                    float d   = (sp * lat) * gabs;
                    unsigned idx = (unsigned)row * (unsigned)WID_ + (unsigned)(col + q);
                    unsigned bits = rbits32(idx);
                    float u = __uint_as_float((bits >> 9) | 0x3f800000u) - 1.0f;
                    float spike;
                    if (d >= 10.0f) spike = 1.0f;
                    else {
                        float t = __expf(-d);
                        spike = (u > t) ? 1.0f : 0.0f;
                        if (fabsf(u - t) < MARGIN * t) {
                            unsigned w = atomicAdd(&g_count, 1u);
                            if (w < WCAP) g_worklist[w] = idx;
                        }
                    }
                    if (q) { dv.y = d; sv.y = spike; } else { dv.x = d; sv.x = spike; }
                }
                size_t ob = (size_t)row * WID_ + col;
                *reinterpret_cast<float2*>(drv + ob) = dv;
                *reinterpret_cast<float2*>(spk + ob) = sv;
            }
        }
}

// ---------------- exact fp32 fixup for borderline spikes (reference semantics) --------
__global__ void fixup_k(const float* __restrict__ co, const float* __restrict__ qfc1,
                        const float* __restrict__ bias, const float* __restrict__ latent,
                        const float* __restrict__ gainp, float* __restrict__ spk)
{
    __shared__ float red[4];
    const unsigned n = (g_count < WCAP) ? g_count : WCAP;
    const float gabs = fabsf(gainp[0]);
    const int tid = threadIdx.x;   // 128
    for (unsigned i = blockIdx.x; i < n; i += gridDim.x) {
        unsigned idx = g_worklist[i];
        int row = idx >> 12, col = idx & (WID_-1);
        const float* cr = co + (size_t)row * RED_;
        const float* wr = qfc1 + (size_t)col * RED_;
        float s = cr[tid]*wr[tid] + cr[tid+128]*wr[tid+128];
        #pragma unroll
        for (int o = 16; o; o >>= 1) s += __shfl_xor_sync(0xffffffffu, s, o);
        if ((tid & 31) == 0) red[tid >> 5] = s;
        __syncthreads();
        if (tid == 0) {
            float pre = (red[0]+red[1]) + (red[2]+red[3]) + bias[col];
            float spl = fmaxf(pre, 0.0f) + log1pf(expf(-fabsf(pre)));
            float d   = (spl * latent[row % T_]) * gabs;
            unsigned bits = rbits32(idx);
            float u = __uint_as_float((bits >> 9) | 0x3f800000u) - 1.0f;
            spk[idx] = (d >= 10.0f) ? 1.0f : ((logf(u) > -d) ? 1.0f : 0.0f);
        }
        __syncthreads();
    }
}

// ---------------- decay-weighted temporal reduction (latency-optimized) ---------------
__global__ void weighted_k(const float* __restrict__ spikes) {
    int idx = blockIdx.x * blockDim.x + threadIdx.x;
    if (idx >= B_*WID_) return;
    int b = idx >> 12, w = idx & (WID_-1);
    const float* sp = spikes + (size_t)b*T_*WID_ + w;
    float s0 = 0.0f, s1 = 0.0f, s2 = 0.0f, s3 = 0.0f;
    #pragma unroll
    for (int t = 0; t < T_; t += 4) {
        s0 = fmaf(__ldg(sp + (size_t)(t+0)*WID_), g_decay[t+0], s0);
        s1 = fmaf(__ldg(sp + (size_t)(t+1)*WID_), g_decay[t+1], s1);
        s2 = fmaf(__ldg(sp + (size_t)(t+2)*WID_), g_decay[t+2], s2);
        s3 = fmaf(__ldg(sp + (size_t)(t+3)*WID_), g_decay[t+3], s3);
    }
    g_wsum[idx] = (s0 + s1) + (s2 + s3);
}

// ---------------- logits ----------------
__global__ void logits_k(const float* __restrict__ bias, float* __restrict__ out) {
    int bc = blockIdx.x;
    int b = bc / CLS_, c = bc % CLS_;
    const float* wr = g_wsum + (size_t)b*WID_;
    const float* fr = g_qfc2 + (size_t)c*WID_;
    float s = 0.0f;
    for (int i = threadIdx.x; i < WID_; i += 128) s += wr[i]*fr[i];
    #pragma unroll
    for (int o = 16; o; o >>= 1) s += __shfl_xor_sync(0xffffffffu, s, o);
    __shared__ float red[4];
    if ((threadIdx.x & 31) == 0) red[threadIdx.x >> 5] = s;
    __syncthreads();
    if (threadIdx.x == 0) out[bc] = (red[0]+red[1]+red[2]+red[3]) + bias[c];
}

// ---------------- launcher ----------------
extern "C" void kernel_launch(void* const* d_in, const int* in_sizes, int n_in,
                              void* d_out, int out_size) {
    (void)in_sizes; (void)n_in; (void)out_size;
    const float* x        = (const float*)d_in[0];
    const float* latent   = (const float*)d_in[1];
    const float* spatialW = (const float*)d_in[2];
    const float* spatialB = (const float*)d_in[3];
    const float* convW    = (const float*)d_in[4];
    const float* convB    = (const float*)d_in[5];
    const float* fc1W     = (const float*)d_in[6];
    const float* fc1B     = (const float*)d_in[7];
    const float* fc2W     = (const float*)d_in[8];
    const float* fc2B     = (const float*)d_in[9];
    const float* gain     = (const float*)d_in[10];

    float* out        = (float*)d_out;
    float* out_logits = out;
    float* out_spk    = out + (CLS_*B_);
    float* out_drv    = out + (CLS_*B_) + (size_t)NELEM_;

    float *qksp, *qfc1, *qk, *qfc2, *cwt, *xp, *co, *coh;
    cudaGetSymbolAddress((void**)&qksp, g_qksp);
    cudaGetSymbolAddress((void**)&qfc1, g_qfc1);
    cudaGetSymbolAddress((void**)&qk,   g_qk);
    cudaGetSymbolAddress((void**)&qfc2, g_qfc2);
    cudaGetSymbolAddress((void**)&cwt,  g_convWt);
    cudaGetSymbolAddress((void**)&xp,   g_xp);
    cudaGetSymbolAddress((void**)&co,   g_co);
    cudaGetSymbolAddress((void**)&coh,  g_coh);

    static bool attr_set = false;
    if (!attr_set) {
        cudaFuncSetAttribute(g2tf_k, cudaFuncAttributeMaxDynamicSharedMemorySize, G2_SMEM);
        cudaFuncSetAttribute(g1tf_k, cudaFuncAttributeMaxDynamicSharedMemorySize, G1_SMEM);
        attr_set = true;
    }

    init_k<<<1, 128>>>();
    absmax3_k<<<384, 256>>>(spatialW, fc1W, fc2W);
    prep_k<<<NPREP_/256, 256>>>(spatialW, fc1W, fc2W, convW);

    // GEMM1 (2-pass exact tf32, int4-level B): xp = relu(scale0*(x @ k_sp^T) + b)
    g1tf_k<<<dim3(RED_/64, ROWS_/128), 256, G1_SMEM>>>(x, qksp, spatialB, xp);
    // conv (fused im2col, exact fp32 FFMA2): co = relu(im2col(xp) @ cwt^T + cb), + coh
    conv_k<<<dim3(RED_/128, ROWS_/128), 256>>>(xp, cwt, convB, co, coh);
    // GEMM2 (tf32 1-pass, int4-level B, scale factored) + drive/spike + flags
    g2tf_k<<<dim3(WID_/64, ROWS_/128), 256, G2_SMEM>>>(coh, qk, fc1B,
                                                       latent, gain, out_drv, out_spk);
    // exact recompute of borderline spikes
    fixup_k<<<2048, 128>>>(co, qfc1, fc1B, latent, gain, out_spk);
    weighted_k<<<(B_*WID_ + 255)/256, 256>>>(out_spk);
    logits_k<<<B_*CLS_, 128>>>(fc2B, out_logits);
}

// round 16
// speedup vs baseline: 1.3846x; 1.0818x over previous
#include <cuda_runtime.h>
#include <cuda_bf16.h>
#include <cstdint>

// ---------------- problem dims ----------------
#define B_    64
#define T_    100
#define INF_  700
#define RED_  256
#define WID_  4096
#define CLS_  20
#define ROWS_ (B_*T_)          // 6400
#define KC_   1280             // conv im2col K (256*5)
#define NELEM_ (ROWS_*WID_)    // 26214400
#define WCAP  (1u<<22)
#define MARGIN 2.5e-3f

#define N0_ (RED_*INF_)        // 179200
#define N1_ (WID_*RED_)        // 1048576
#define N2_ (CLS_*WID_)        // 81920
#define N3_ (RED_*KC_)         // 327680
#define NPREP_ (N0_+N1_+N2_+N3_)   // 1637376 = 6396*256

// ---------------- scratch (static device globals; no alloc allowed) ----------------
__device__ unsigned g_absmax[4];
__device__ unsigned g_count;
__device__ unsigned g_worklist[WCAP];
__device__ float  g_decay[T_];
__device__ float  g_qksp[RED_*INF_];      // integer levels of spatial_W (tf32-exact)
__device__ float  g_qfc1[WID_*RED_];      // exact scale*k (fixup)
__device__ unsigned short g_qkb[WID_*RED_];   // integer k of fc1 as bf16 (exact)
__device__ float  g_qfc2[CLS_*WID_];
__device__ float  g_convWt[RED_*KC_];
__device__ float  g_xp[ROWS_*RED_];
__device__ float  g_co[ROWS_*RED_];       // exact (fixup)
__device__ unsigned short g_cohb[ROWS_*RED_]; // bf16 of co
__device__ float  g_wsum[B_*WID_];

// ---------------- threefry2x32 (JAX-compatible, partitionable mode) ----------------
__host__ __device__ constexpr unsigned rotl32c(unsigned v, int s) {
    return (v << s) | (v >> (32 - s));
}
struct K2 { unsigned a, b; };
constexpr K2 tf_const(unsigned k0, unsigned k1, unsigned x0, unsigned x1) {
    unsigned ks2 = k0 ^ k1 ^ 0x1BD11BDAu;
    unsigned ks[3] = {k0, k1, ks2};
    x0 += k0; x1 += k1;
    const int R[20] = {13,15,26,6, 17,29,16,24, 13,15,26,6, 17,29,16,24, 13,15,26,6};
    for (int g = 0; g < 5; ++g) {
        for (int j = 0; j < 4; ++j) { x0 += x1; x1 = rotl32c(x1, R[g*4+j]); x1 ^= x0; }
        x0 += ks[(g+1)%3];
        x1 += ks[(g+2)%3] + (unsigned)(g+1);
    }
    return K2{x0, x1};
}
constexpr K2 SUBKEY = tf_const(0u, 42u, 0u, 1u);
constexpr unsigned SK0 = SUBKEY.a;
constexpr unsigned SK1 = SUBKEY.b;

__device__ __forceinline__ uint2 tf2x32(unsigned k0, unsigned k1, unsigned x0, unsigned x1) {
    unsigned ks2 = k0 ^ k1 ^ 0x1BD11BDAu;
    x0 += k0; x1 += k1;
#define TFR(r) { x0 += x1; x1 = __funnelshift_l(x1, x1, (r)); x1 ^= x0; }
    TFR(13) TFR(15) TFR(26) TFR(6)   x0 += k1;  x1 += ks2 + 1u;
    TFR(17) TFR(29) TFR(16) TFR(24)  x0 += ks2; x1 += k0  + 2u;
    TFR(13) TFR(15) TFR(26) TFR(6)   x0 += k0;  x1 += k1  + 3u;
    TFR(17) TFR(29) TFR(16) TFR(24)  x0 += k1;  x1 += ks2 + 4u;
    TFR(13) TFR(15) TFR(26) TFR(6)   x0 += ks2; x1 += k0  + 5u;
#undef TFR
    return make_uint2(x0, x1);
}
__device__ __forceinline__ unsigned rbits32(unsigned idx) {
    uint2 r = tf2x32(SK0, SK1, 0u, idx);
    return r.x ^ r.y;
}

// ---------------- packed f32x2 helpers ----------------
__device__ __forceinline__ void ffma2(unsigned long long& acc,
                                      unsigned long long a,
                                      unsigned long long b) {
    asm("fma.rn.f32x2 %0, %1, %2, %0;" : "+l"(acc) : "l"(a), "l"(b));
}
__device__ __forceinline__ unsigned long long dup_f32x2(float x) {
    unsigned long long d;
    asm("mov.b64 %0, {%1, %1};" : "=l"(d) : "f"(x));
    return d;
}
__device__ __forceinline__ float2 unpack_f32x2(unsigned long long v) {
    float lo, hi;
    asm("mov.b64 {%0, %1}, %2;" : "=f"(lo), "=f"(hi) : "l"(v));
    return make_float2(lo, hi);
}

// ---------------- tf32 / bf16 helpers ----------------
__device__ __forceinline__ float tf32_hi(float x) {
    uint32_t u; asm("cvt.rna.tf32.f32 %0, %1;" : "=r"(u) : "f"(x));
    return __uint_as_float(u);
}
#define MMA_TF32(c, a, b) \
    asm volatile("mma.sync.aligned.m16n8k8.row.col.f32.tf32.tf32.f32 " \
        "{%0,%1,%2,%3}, {%4,%5,%6,%7}, {%8,%9}, {%0,%1,%2,%3};" \
        : "+f"((c)[0]), "+f"((c)[1]), "+f"((c)[2]), "+f"((c)[3]) \
        : "r"(__float_as_uint((a)[0])), "r"(__float_as_uint((a)[1])), \
          "r"(__float_as_uint((a)[2])), "r"(__float_as_uint((a)[3])), \
          "r"(__float_as_uint((b)[0])), "r"(__float_as_uint((b)[1])))
#define MMA_BF16(c, a0, a1, a2, a3, b0, b1) \
    asm volatile("mma.sync.aligned.m16n8k16.row.col.f32.bf16.bf16.f32 " \
        "{%0,%1,%2,%3}, {%4,%5,%6,%7}, {%8,%9}, {%0,%1,%2,%3};" \
        : "+f"((c)[0]), "+f"((c)[1]), "+f"((c)[2]), "+f"((c)[3]) \
        : "r"(a0), "r"(a1), "r"(a2), "r"(a3), "r"(b0), "r"(b1))

__device__ __forceinline__ unsigned short bf16_of(float x) {
    unsigned short u;
    asm("cvt.rn.bf16.f32 %0, %1;" : "=h"(u) : "f"(x));
    return u;
}
__device__ __forceinline__ uint32_t bf16x2_of(float lo, float hi) {
    uint32_t u;
    asm("cvt.rn.bf16x2.f32 %0, %1, %2;" : "=r"(u) : "f"(hi), "f"(lo));
    return u;
}

__device__ __forceinline__ uint32_t smem_u32(const void* p) {
    uint32_t a;
    asm("{ .reg .u64 t; cvta.to.shared.u64 t, %1; cvt.u32.u64 %0, t; }" : "=r"(a) : "l"(p));
    return a;
}
#define CP_ASYNC16(s, g) \
    asm volatile("cp.async.cg.shared.global [%0], [%1], 16;" :: "r"(s), "l"(g))
#define CP_COMMIT()  asm volatile("cp.async.commit_group;")
#define CP_WAIT0()   asm volatile("cp.async.wait_group 0;")

// ---------------- prep kernels ----------------
__global__ void init_k() {
    if (threadIdx.x < 4) g_absmax[threadIdx.x] = 0u;
    if (threadIdx.x == 0) g_count = 0u;
    if (threadIdx.x < T_)
        g_decay[threadIdx.x] = expf(-2.0f + (float)threadIdx.x * (2.0f/99.0f));
}
__global__ void absmax3_k(const float* __restrict__ W0, const float* __restrict__ W1,
                          const float* __restrict__ W2) {
    const float* W; int n, which, b0, nb;
    if (blockIdx.x < 64)        { W = W0; n = N0_; which = 0; b0 = 0;   nb = 64;  }
    else if (blockIdx.x < 320)  { W = W1; n = N1_; which = 1; b0 = 64;  nb = 256; }
    else                        { W = W2; n = N2_; which = 2; b0 = 320; nb = 64;  }
    float m = 0.0f;
    for (int i = (int)(blockIdx.x - b0)*blockDim.x + threadIdx.x; i < n; i += nb*blockDim.x)
        m = fmaxf(m, fabsf(W[i]));
    #pragma unroll
    for (int o = 16; o; o >>= 1) m = fmaxf(m, __shfl_xor_sync(0xffffffffu, m, o));
    if ((threadIdx.x & 31) == 0) atomicMax(&g_absmax[which], __float_as_uint(m));
}
__global__ void prep_k(const float* __restrict__ spW, const float* __restrict__ fc1W,
                       const float* __restrict__ fc2W, const float* __restrict__ convW) {
    int i = blockIdx.x*blockDim.x + threadIdx.x;
    if (i < N0_) {
        float scale = fmaxf(__fdiv_rn(__uint_as_float(g_absmax[0]), 7.0f), 1e-8f);
        g_qksp[i] = rintf(__fdiv_rn(spW[i], scale));
    } else if (i < N0_ + N1_) {
        int j = i - N0_;
        float scale = fmaxf(__fdiv_rn(__uint_as_float(g_absmax[1]), 7.0f), 1e-8f);
        float k = rintf(__fdiv_rn(fc1W[j], scale));
        g_qfc1[j] = __fmul_rn(k, scale);
        g_qkb[j]  = bf16_of(k);
    } else if (i < N0_ + N1_ + N2_) {
        int j = i - N0_ - N1_;
        float scale = fmaxf(__fdiv_rn(__uint_as_float(g_absmax[2]), 7.0f), 1e-8f);
        g_qfc2[j] = __fmul_rn(rintf(__fdiv_rn(fc2W[j], scale)), scale);
    } else {
        int j = i - N0_ - N1_ - N2_;
        int o = j / KC_, rem = j % KC_;
        int k = rem >> 8, c = rem & 255;
        g_convWt[j] = convW[o*KC_ + c*5 + k];
    }
}

// ---------------- GEMM1: 2-pass exact tf32 (A = x hi/lo split, B = int4 levels) ------
#define G1AST 20
#define G1ASZ (128*G1AST)
#define G1BSZ (64*G1AST)
#define G1_SMEM ((2*2*G1ASZ + 2*G1BSZ)*4)

__global__ __launch_bounds__(256, 2)
void g1tf_k(const float* __restrict__ x, const float* __restrict__ qksp,
            const float* __restrict__ bias, float* __restrict__ xp)
{
    extern __shared__ float smf[];
    float* sAh = smf;
    float* sAl = smf + 2*G1ASZ;
    float* sBp = smf + 4*G1ASZ;

    const int tid  = threadIdx.x;
    const int lane = tid & 31;
    const int wid  = tid >> 5;
    const int wm   = (wid & 3) * 32;
    const int wn   = (wid >> 2) * 32;
    const int bm0  = blockIdx.y * 128, bn0 = blockIdx.x * 64;
    const int K = INF_;
    const int nch = (K + 15) >> 4;

    float acc[2][4][4];
    #pragma unroll
    for (int mi = 0; mi < 2; ++mi)
        #pragma unroll
        for (int ni = 0; ni < 4; ++ni)
            #pragma unroll
            for (int q = 0; q < 4; ++q) acc[mi][ni][q] = 0.0f;

    float4 va[2], vb;
    {
        #pragma unroll
        for (int i = 0; i < 2; ++i) {
            int q = tid + 256*i;
            int row = q >> 2, c = (q & 3) * 4;
            va[i] = (c < K) ? *reinterpret_cast<const float4*>(x + (size_t)(bm0+row)*K + c)
                            : make_float4(0,0,0,0);
        }
        {
            int row = tid >> 2, c = (tid & 3) * 4;
            vb = (c < K) ? *reinterpret_cast<const float4*>(qksp + (size_t)(bn0+row)*K + c)
                         : make_float4(0,0,0,0);
        }
        #pragma unroll
        for (int i = 0; i < 2; ++i) {
            int q = tid + 256*i;
            int row = q >> 2, c4 = (q & 3) * 4;
            float4 h, l;
            h.x = tf32_hi(va[i].x); l.x = tf32_hi(va[i].x - h.x);
            h.y = tf32_hi(va[i].y); l.y = tf32_hi(va[i].y - h.y);
            h.z = tf32_hi(va[i].z); l.z = tf32_hi(va[i].z - h.z);
            h.w = tf32_hi(va[i].w); l.w = tf32_hi(va[i].w - h.w);
            *reinterpret_cast<float4*>(sAh + row*G1AST + c4) = h;
            *reinterpret_cast<float4*>(sAl + row*G1AST + c4) = l;
        }
        {
            int row = tid >> 2, c4 = (tid & 3) * 4;
            *reinterpret_cast<float4*>(sBp + row*G1AST + c4) = vb;
        }
        __syncthreads();
    }

    int p = 0;
    for (int ch = 0; ch < nch; ++ch) {
        const bool more = (ch + 1 < nch);
        if (more) {
            int k0 = (ch + 1) * 16;
            #pragma unroll
            for (int i = 0; i < 2; ++i) {
                int q = tid + 256*i;
                int row = q >> 2, c = k0 + (q & 3) * 4;
                va[i] = (c < K) ? *reinterpret_cast<const float4*>(x + (size_t)(bm0+row)*K + c)
                                : make_float4(0,0,0,0);
            }
            {
                int row = tid >> 2, c = k0 + (tid & 3) * 4;
                vb = (c < K) ? *reinterpret_cast<const float4*>(qksp + (size_t)(bn0+row)*K + c)
                             : make_float4(0,0,0,0);
            }
        }
        const float* Ah = sAh + p*G1ASZ;
        const float* Al = sAl + p*G1ASZ;
        const float* Bp = sBp + p*G1BSZ;
        #pragma unroll
        for (int ksl = 0; ksl < 2; ++ksl) {
            const int bc = ksl*8 + (lane & 3);
            float ah[2][4], al[2][4];
            #pragma unroll
            for (int mi = 0; mi < 2; ++mi) {
                int r = wm + (lane >> 2) + mi*16;
                ah[mi][0] = Ah[r*G1AST + bc];
                ah[mi][1] = Ah[(r+8)*G1AST + bc];
                ah[mi][2] = Ah[r*G1AST + bc + 4];
                ah[mi][3] = Ah[(r+8)*G1AST + bc + 4];
                al[mi][0] = Al[r*G1AST + bc];
                al[mi][1] = Al[(r+8)*G1AST + bc];
                al[mi][2] = Al[r*G1AST + bc + 4];
                al[mi][3] = Al[(r+8)*G1AST + bc + 4];
            }
            float bfr[4][2];
            #pragma unroll
            for (int ni = 0; ni < 4; ++ni) {
                int n = wn + ni*8 + (lane >> 2);
                bfr[ni][0] = Bp[n*G1AST + bc];
                bfr[ni][1] = Bp[n*G1AST + bc + 4];
            }
            #pragma unroll
            for (int mi = 0; mi < 2; ++mi)
                #pragma unroll
                for (int ni = 0; ni < 4; ++ni) {
                    MMA_TF32(acc[mi][ni], ah[mi], bfr[ni]);
                    MMA_TF32(acc[mi][ni], al[mi], bfr[ni]);
                }
        }
        if (more) {
            int q2 = p ^ 1;
            float* Ah2 = sAh + q2*G1ASZ;
            float* Al2 = sAl + q2*G1ASZ;
            float* Bp2 = sBp + q2*G1BSZ;
            #pragma unroll
            for (int i = 0; i < 2; ++i) {
                int q = tid + 256*i;
                int row = q >> 2, c4 = (q & 3) * 4;
                float4 h, l;
                h.x = tf32_hi(va[i].x); l.x = tf32_hi(va[i].x - h.x);
                h.y = tf32_hi(va[i].y); l.y = tf32_hi(va[i].y - h.y);
                h.z = tf32_hi(va[i].z); l.z = tf32_hi(va[i].z - h.z);
                h.w = tf32_hi(va[i].w); l.w = tf32_hi(va[i].w - h.w);
                *reinterpret_cast<float4*>(Ah2 + row*G1AST + c4) = h;
                *reinterpret_cast<float4*>(Al2 + row*G1AST + c4) = l;
            }
            {
                int row = tid >> 2, c4 = (tid & 3) * 4;
                *reinterpret_cast<float4*>(Bp2 + row*G1AST + c4) = vb;
            }
            __syncthreads();
            p = q2;
        }
    }

    const int r0 = bm0 + wm + (lane >> 2);
    const int c0 = bn0 + wn + (lane & 3)*2;
    const float scale0 = fmaxf(__fdiv_rn(__uint_as_float(g_absmax[0]), 7.0f), 1e-8f);

    #pragma unroll
    for (int mi = 0; mi < 2; ++mi)
        #pragma unroll
        for (int ni = 0; ni < 4; ++ni) {
            int col = c0 + ni*8;
            float b0 = __ldg(bias + col), b1 = __ldg(bias + col + 1);
            #pragma unroll
            for (int h = 0; h < 2; ++h) {
                int row = r0 + mi*16 + h*8;
                float2 v;
                v.x = fmaxf(fmaf(acc[mi][ni][h*2+0], scale0, b0), 0.0f);
                v.y = fmaxf(fmaf(acc[mi][ni][h*2+1], scale0, b1), 0.0f);
                *reinterpret_cast<float2*>(xp + (size_t)row*RED_ + col) = v;
            }
        }
}

// ---------------- conv: FFMA2 double-buffered SGEMM 128x128x16 (exact fp32) ----------
__device__ __forceinline__ float4 ldA_conv(const float* __restrict__ A, int row, int c) {
    int tap = c >> 8, chn = c & 255;
    int b = row / T_, t = row - b*T_;
    int ts = t + tap - 2;
    if (ts < 0 || ts >= T_) return make_float4(0,0,0,0);
    return *reinterpret_cast<const float4*>(A + (size_t)(b*T_ + ts)*RED_ + chn);
}

__global__ __launch_bounds__(256, 2)
void conv_k(const float* __restrict__ A, const float* __restrict__ B,
            const float* __restrict__ bias, float* __restrict__ C,
            unsigned short* __restrict__ Chb)
{
    __shared__ float sA[2][16][128];
    __shared__ float sB[2][16][128];

    const int K = KC_, N = RED_;
    const int tid  = threadIdx.x;
    const int lane = tid & 31;
    const int wid  = tid >> 5;
    const int lr   = lane >> 2;
    const int lc   = lane & 3;
    const int wm   = (wid & 1) * 64;
    const int wn   = (wid >> 1) * 32;
    const int bm0  = blockIdx.y * 128, bn0 = blockIdx.x * 128;

    unsigned long long acc2[2][2][4][2];
    #pragma unroll
    for (int im = 0; im < 2; ++im)
        #pragma unroll
        for (int in = 0; in < 2; ++in)
            #pragma unroll
            for (int i = 0; i < 4; ++i) {
                acc2[im][in][i][0] = 0ull;
                acc2[im][in][i][1] = 0ull;
            }

    const int nch = (K + 15) >> 4;
    float4 va[2], vb[2];

    {
        #pragma unroll
        for (int i = 0; i < 2; ++i) {
            int q = tid + 256*i;
            int row = q >> 2, c = (q & 3) * 4;
            va[i] = ldA_conv(A, bm0 + row, c);
            vb[i] = *reinterpret_cast<const float4*>(B + (size_t)(bn0+row)*K + c);
        }
        #pragma unroll
        for (int i = 0; i < 2; ++i) {
            int q = tid + 256*i;
            int row = q >> 2, c4 = (q & 3) * 4;
            sA[0][c4+0][row] = va[i].x; sA[0][c4+1][row] = va[i].y;
            sA[0][c4+2][row] = va[i].z; sA[0][c4+3][row] = va[i].w;
            sB[0][c4+0][row] = vb[i].x; sB[0][c4+1][row] = vb[i].y;
            sB[0][c4+2][row] = vb[i].z; sB[0][c4+3][row] = vb[i].w;
        }
        __syncthreads();
    }

    int p = 0;
    for (int ch = 0; ch < nch; ++ch) {
        const bool more = (ch + 1 < nch);
        if (more) {
            int k0 = (ch + 1) * 16;
            #pragma unroll
            for (int i = 0; i < 2; ++i) {
                int q = tid + 256*i;
                int row = q >> 2, c = k0 + (q & 3) * 4;
                va[i] = ldA_conv(A, bm0 + row, c);
                vb[i] = *reinterpret_cast<const float4*>(B + (size_t)(bn0+row)*K + c);
            }
        }
        #pragma unroll
        for (int kk = 0; kk < 16; ++kk) {
            float4 a0 = *reinterpret_cast<const float4*>(&sA[p][kk][wm + lr*4]);
            float4 a1 = *reinterpret_cast<const float4*>(&sA[p][kk][wm + 32 + lr*4]);
            ulonglong2 b0 = *reinterpret_cast<const ulonglong2*>(&sB[p][kk][wn + lc*4]);
            ulonglong2 b1 = *reinterpret_cast<const ulonglong2*>(&sB[p][kk][wn + 16 + lc*4]);
            unsigned long long bp[2][2] = { { b0.x, b0.y }, { b1.x, b1.y } };
            const float av[2][4] = { { a0.x, a0.y, a0.z, a0.w },
                                     { a1.x, a1.y, a1.z, a1.w } };
            #pragma unroll
            for (int im = 0; im < 2; ++im)
                #pragma unroll
                for (int i = 0; i < 4; ++i) {
                    unsigned long long ad = dup_f32x2(av[im][i]);
                    #pragma unroll
                    for (int in = 0; in < 2; ++in) {
                        ffma2(acc2[im][in][i][0], ad, bp[in][0]);
                        ffma2(acc2[im][in][i][1], ad, bp[in][1]);
                    }
                }
        }
        if (more) {
            int q2 = p ^ 1;
            #pragma unroll
            for (int i = 0; i < 2; ++i) {
                int q = tid + 256*i;
                int row = q >> 2, c4 = (q & 3) * 4;
                sA[q2][c4+0][row] = va[i].x; sA[q2][c4+1][row] = va[i].y;
                sA[q2][c4+2][row] = va[i].z; sA[q2][c4+3][row] = va[i].w;
                sB[q2][c4+0][row] = vb[i].x; sB[q2][c4+1][row] = vb[i].y;
                sB[q2][c4+2][row] = vb[i].z; sB[q2][c4+3][row] = vb[i].w;
            }
            __syncthreads();
            p = q2;
        }
    }

    #pragma unroll
    for (int im = 0; im < 2; ++im)
        #pragma unroll
        for (int i = 0; i < 4; ++i) {
            int row = bm0 + wm + im*32 + lr*4 + i;
            #pragma unroll
            for (int in = 0; in < 2; ++in) {
                int col = bn0 + wn + in*16 + lc*4;
                float2 p01 = unpack_f32x2(acc2[im][in][i][0]);
                float2 p23 = unpack_f32x2(acc2[im][in][i][1]);
                float4 v;
                v.x = fmaxf(p01.x + __ldg(bias + col + 0), 0.0f);
                v.y = fmaxf(p01.y + __ldg(bias + col + 1), 0.0f);
                v.z = fmaxf(p23.x + __ldg(bias + col + 2), 0.0f);
                v.w = fmaxf(p23.y + __ldg(bias + col + 3), 0.0f);
                *reinterpret_cast<float4*>(C + (size_t)row*N + col) = v;
                uint2 hb;
                hb.x = bf16x2_of(v.x, v.y);
                hb.y = bf16x2_of(v.z, v.w);
                *reinterpret_cast<uint2*>(Chb + (size_t)row*N + col) = hb;
            }
        }
}

// ---------------- GEMM2: 1-pass bf16 m16n8k16 (A = bf16(co), B = int4 levels) --------
#define ASTH 40                           // padded k-stride in halves
#define ASZH (128*ASTH)                   // 5120 halves
#define BSZH (64*ASTH)                    // 2560 halves
#define G2_SMEM ((2*ASZH + 2*BSZH)*2)     // 30720 B

__device__ __forceinline__ void g2_issue(const unsigned short* __restrict__ cohb,
                                         const unsigned short* __restrict__ qkb,
                                         uint32_t sAa, uint32_t sBa,
                                         int bm0, int bn0, int k0, int tid) {
    #pragma unroll
    for (int i = 0; i < 2; ++i) {
        int cid = tid + 256*i;
        int row = cid >> 2, ko = (cid & 3) * 8;
        const unsigned short* g = cohb + (size_t)(bm0+row)*RED_ + k0 + ko;
        CP_ASYNC16(sAa + (uint32_t)((row*ASTH + ko) * 2), g);
    }
    {
        int row = tid >> 2, ko = (tid & 3) * 8;
        const unsigned short* g = qkb + (size_t)(bn0+row)*RED_ + k0 + ko;
        CP_ASYNC16(sBa + (uint32_t)((row*ASTH + ko) * 2), g);
    }
    CP_COMMIT();
}

__global__ __launch_bounds__(256, 3)
void g2bf_k(const unsigned short* __restrict__ cohb, const unsigned short* __restrict__ qkb,
            const float* __restrict__ bias,
            const float* __restrict__ latent, const float* __restrict__ gainp,
            float* __restrict__ drv, float* __restrict__ spk)
{
    extern __shared__ unsigned short smu[];
    const uint32_t smem_base = smem_u32(smu);

    const int tid  = threadIdx.x;
    const int lane = tid & 31;
    const int wid  = tid >> 5;
    const int wm   = (wid & 3) * 32;
    const int wn   = (wid >> 2) * 32;
    const int bm0  = blockIdx.y * 128, bn0 = blockIdx.x * 64;

    float acc[2][4][4];
    #pragma unroll
    for (int mi = 0; mi < 2; ++mi)
        #pragma unroll
        for (int ni = 0; ni < 4; ++ni)
            #pragma unroll
            for (int q = 0; q < 4; ++q) acc[mi][ni][q] = 0.0f;

    g2_issue(cohb, qkb, smem_base, smem_base + 2*ASZH*2, bm0, bn0, 0, tid);

    #pragma unroll 1
    for (int ch = 0; ch < 8; ++ch) {
        CP_WAIT0();
        __syncthreads();
        const int p = ch & 1;
        if (ch + 1 < 8) {
            const int q2 = p ^ 1;
            g2_issue(cohb, qkb, smem_base + (uint32_t)(q2*ASZH*2),
                     smem_base + (uint32_t)((2*ASZH + q2*BSZH)*2), bm0, bn0, (ch+1)*32, tid);
        }
        const unsigned short* A2 = smu + p*ASZH;
        const unsigned short* B2 = smu + 2*ASZH + p*BSZH;
        #pragma unroll
        for (int ksl = 0; ksl < 2; ++ksl) {
            const int c = ksl*16 + (lane & 3)*2;
            uint32_t afr[2][4];
            #pragma unroll
            for (int mi = 0; mi < 2; ++mi) {
                int r = wm + (lane >> 2) + mi*16;
                afr[mi][0] = *reinterpret_cast<const uint32_t*>(A2 + r*ASTH + c);
                afr[mi][1] = *reinterpret_cast<const uint32_t*>(A2 + (r+8)*ASTH + c);
                afr[mi][2] = *reinterpret_cast<const uint32_t*>(A2 + r*ASTH + c + 8);
                afr[mi][3] = *reinterpret_cast<const uint32_t*>(A2 + (r+8)*ASTH + c + 8);
            }
            uint32_t bfr[4][2];
            #pragma unroll
            for (int ni = 0; ni < 4; ++ni) {
                int n = wn + ni*8 + (lane >> 2);
                bfr[ni][0] = *reinterpret_cast<const uint32_t*>(B2 + n*ASTH + c);
                bfr[ni][1] = *reinterpret_cast<const uint32_t*>(B2 + n*ASTH + c + 8);
            }
            #pragma unroll
            for (int mi = 0; mi < 2; ++mi)
                #pragma unroll
                for (int ni = 0; ni < 4; ++ni)
                    MMA_BF16(acc[mi][ni], afr[mi][0], afr[mi][1], afr[mi][2], afr[mi][3],
                             bfr[ni][0], bfr[ni][1]);
        }
    }

    const int r0 = bm0 + wm + (lane >> 2);
    const int c0 = bn0 + wn + (lane & 3)*2;
    const float gabs = fabsf(gainp[0]);
    const float scaleB = fmaxf(__fdiv_rn(__uint_as_float(g_absmax[1]), 7.0f), 1e-8f);

    #pragma unroll
    for (int mi = 0; mi < 2; ++mi)
        #pragma unroll
        for (int ni = 0; ni < 4; ++ni) {
            int col = c0 + ni*8;
            float b0 = __ldg(bias + col), b1 = __ldg(bias + col + 1);
            #pragma unroll
            for (int h = 0; h < 2; ++h) {
                int row = r0 + mi*16 + h*8;
                float lat = __ldg(latent + (row % T_));
                float2 dv, sv;
                #pragma unroll
                for (int q = 0; q < 2; ++q) {
                    float pre = fmaf(acc[mi][ni][h*2+q], scaleB, q ? b1 : b0);
                    float e   = __expf(-fabsf(pre));
                    float sp  = fmaxf(pre, 0.0f) + __logf(1.0f + e);
                    float d   = (sp * lat) * gabs;
                    unsigned idx = (unsigned)row * (unsigned)WID_ + (unsigned)(col + q);
                    unsigned bits = rbits32(idx);
                    float u = __uint_as_float((bits >> 9) | 0x3f800000u) - 1.0f;
                    float spike;
                    if (d >= 10.0f) spike = 1.0f;
                    else {
                        float t = __expf(-d);
                        spike = (u > t) ? 1.0f : 0.0f;
                        if (fabsf(u - t) < MARGIN * t) {
                            unsigned w = atomicAdd(&g_count, 1u);
                            if (w < WCAP) g_worklist[w] = idx;
                        }
                    }
                    if (q) { dv.y = d; sv.y = spike; } else { dv.x = d; sv.x = spike; }
                }
                size_t ob = (size_t)row * WID_ + col;
                *reinterpret_cast<float2*>(drv + ob) = dv;
                *reinterpret_cast<float2*>(spk + ob) = sv;
            }
        }
}

// ---------------- exact fp32 fixup for borderline spikes (reference semantics) --------
__global__ void fixup_k(const float* __restrict__ co, const float* __restrict__ qfc1,
                        const float* __restrict__ bias, const float* __restrict__ latent,
                        const float* __restrict__ gainp, float* __restrict__ spk)
{
    __shared__ float red[4];
    const unsigned n = (g_count < WCAP) ? g_count : WCAP;
    const float gabs = fabsf(gainp[0]);
    const int tid = threadIdx.x;   // 128
    for (unsigned i = blockIdx.x; i < n; i += gridDim.x) {
        unsigned idx = g_worklist[i];
        int row = idx >> 12, col = idx & (WID_-1);
        const float* cr = co + (size_t)row * RED_;
        const float* wr = qfc1 + (size_t)col * RED_;
        float s = cr[tid]*wr[tid] + cr[tid+128]*wr[tid+128];
        #pragma unroll
        for (int o = 16; o; o >>= 1) s += __shfl_xor_sync(0xffffffffu, s, o);
        if ((tid & 31) == 0) red[tid >> 5] = s;
        __syncthreads();
        if (tid == 0) {
            float pre = (red[0]+red[1]) + (red[2]+red[3]) + bias[col];
            float spl = fmaxf(pre, 0.0f) + log1pf(expf(-fabsf(pre)));
            float d   = (spl * latent[row % T_]) * gabs;
            unsigned bits = rbits32(idx);
            float u = __uint_as_float((bits >> 9) | 0x3f800000u) - 1.0f;
            spk[idx] = (d >= 10.0f) ? 1.0f : ((logf(u) > -d) ? 1.0f : 0.0f);
        }
        __syncthreads();
    }
}

// ---------------- decay-weighted temporal reduction (latency-optimized) ---------------
__global__ void weighted_k(const float* __restrict__ spikes) {
    int idx = blockIdx.x * blockDim.x + threadIdx.x;
    if (idx >= B_*WID_) return;
    int b = idx >> 12, w = idx & (WID_-1);
    const float* sp = spikes + (size_t)b*T_*WID_ + w;
    float s0 = 0.0f, s1 = 0.0f, s2 = 0.0f, s3 = 0.0f;
    #pragma unroll
    for (int t = 0; t < T_; t += 4) {
        s0 = fmaf(__ldg(sp + (size_t)(t+0)*WID_), g_decay[t+0], s0);
        s1 = fmaf(__ldg(sp + (size_t)(t+1)*WID_), g_decay[t+1], s1);
        s2 = fmaf(__ldg(sp + (size_t)(t+2)*WID_), g_decay[t+2], s2);
        s3 = fmaf(__ldg(sp + (size_t)(t+3)*WID_), g_decay[t+3], s3);
    }
    g_wsum[idx] = (s0 + s1) + (s2 + s3);
}

// ---------------- logits ----------------
__global__ void logits_k(const float* __restrict__ bias, float* __restrict__ out) {
    int bc = blockIdx.x;
    int b = bc / CLS_, c = bc % CLS_;
    const float* wr = g_wsum + (size_t)b*WID_;
    const float* fr = g_qfc2 + (size_t)c*WID_;
    float s = 0.0f;
    for (int i = threadIdx.x; i < WID_; i += 128) s += wr[i]*fr[i];
    #pragma unroll
    for (int o = 16; o; o >>= 1) s += __shfl_xor_sync(0xffffffffu, s, o);
    __shared__ float red[4];
    if ((threadIdx.x & 31) == 0) red[threadIdx.x >> 5] = s;
    __syncthreads();
    if (threadIdx.x == 0) out[bc] = (red[0]+red[1]+red[2]+red[3]) + bias[c];
}

// ---------------- launcher ----------------
extern "C" void kernel_launch(void* const* d_in, const int* in_sizes, int n_in,
                              void* d_out, int out_size) {
    (void)in_sizes; (void)n_in; (void)out_size;
    const float* x        = (const float*)d_in[0];
    const float* latent   = (const float*)d_in[1];
    const float* spatialW = (const float*)d_in[2];
    const float* spatialB = (const float*)d_in[3];
    const float* convW    = (const float*)d_in[4];
    const float* convB    = (const float*)d_in[5];
    const float* fc1W     = (const float*)d_in[6];
    const float* fc1B     = (const float*)d_in[7];
    const float* fc2W     = (const float*)d_in[8];
    const float* fc2B     = (const float*)d_in[9];
    const float* gain     = (const float*)d_in[10];

    float* out        = (float*)d_out;
    float* out_logits = out;
    float* out_spk    = out + (CLS_*B_);
    float* out_drv    = out + (CLS_*B_) + (size_t)NELEM_;

    float *qksp, *qfc1, *qfc2, *cwt, *xp, *co;
    unsigned short *qkb, *cohb;
    cudaGetSymbolAddress((void**)&qksp, g_qksp);
    cudaGetSymbolAddress((void**)&qfc1, g_qfc1);
    cudaGetSymbolAddress((void**)&qkb,  g_qkb);
    cudaGetSymbolAddress((void**)&qfc2, g_qfc2);
    cudaGetSymbolAddress((void**)&cwt,  g_convWt);
    cudaGetSymbolAddress((void**)&xp,   g_xp);
    cudaGetSymbolAddress((void**)&co,   g_co);
    cudaGetSymbolAddress((void**)&cohb, g_cohb);

    static bool attr_set = false;
    if (!attr_set) {
        cudaFuncSetAttribute(g2bf_k, cudaFuncAttributeMaxDynamicSharedMemorySize, G2_SMEM);
        cudaFuncSetAttribute(g1tf_k, cudaFuncAttributeMaxDynamicSharedMemorySize, G1_SMEM);
        attr_set = true;
    }

    init_k<<<1, 128>>>();
    absmax3_k<<<384, 256>>>(spatialW, fc1W, fc2W);
    prep_k<<<NPREP_/256, 256>>>(spatialW, fc1W, fc2W, convW);

    // GEMM1 (2-pass exact tf32, int4-level B): xp = relu(scale0*(x @ k_sp^T) + b)
    g1tf_k<<<dim3(RED_/64, ROWS_/128), 256, G1_SMEM>>>(x, qksp, spatialB, xp);
    // conv (fused im2col, exact fp32 FFMA2): co = relu(im2col(xp) @ cwt^T + cb), + bf16 copy
    conv_k<<<dim3(RED_/128, ROWS_/128), 256>>>(xp, cwt, convB, co, cohb);
    // GEMM2 (bf16 1-pass, int4-level B, scale factored) + drive/spike + flags
    g2bf_k<<<dim3(WID_/64, ROWS_/128), 256, G2_SMEM>>>(cohb, qkb, fc1B,
                                                       latent, gain, out_drv, out_spk);
    // exact recompute of borderline spikes
    fixup_k<<<2048, 128>>>(co, qfc1, fc1B, latent, gain, out_spk);
    weighted_k<<<(B_*WID_ + 255)/256, 256>>>(out_spk);
    logits_k<<<B_*CLS_, 128>>>(fc2B, out_logits);
}